// round 14
// baseline (speedup 1.0000x reference)
#include <cuda_runtime.h>
#include <cuda_bf16.h>
#include <math.h>
#include <stdint.h>

// Problem constants
#define B_  2
#define N_  2048
#define D_  1024
#define H_  16
#define DH_ 64
#define E3_ 192
#define J3_ 3072
#define M_  4096

// ---------------------------------------------------------------------------
// Scratch (device globals)
// ---------------------------------------------------------------------------
__device__ float g_attn[(size_t)B_*H_*N_*N_];
__device__ float g_inv [(size_t)B_*H_*N_];
__device__ float g_psum[(size_t)B_*H_*N_*16];

__device__ __nv_bfloat16 g_xhi [(size_t)M_*D_];
__device__ __nv_bfloat16 g_xlo [(size_t)M_*D_];
__device__ __nv_bfloat16 g_wqhi[(size_t)J3_*D_];
__device__ __nv_bfloat16 g_wqlo[(size_t)J3_*D_];
__device__ __nv_bfloat16 g_wphi[(size_t)D_*D_];
__device__ __nv_bfloat16 g_wplo[(size_t)D_*D_];
__device__ __nv_bfloat16 g_sahi[(size_t)M_*D_];
__device__ __nv_bfloat16 g_salo[(size_t)M_*D_];

__device__ __nv_bfloat16 g_qh[(size_t)B_*H_*N_*DH_];
__device__ __nv_bfloat16 g_ql[(size_t)B_*H_*N_*DH_];
__device__ __nv_bfloat16 g_kh[(size_t)B_*H_*N_*DH_];
__device__ __nv_bfloat16 g_kl[(size_t)B_*H_*N_*DH_];
__device__ __nv_bfloat16 g_vth[(size_t)B_*H_*DH_*N_];
__device__ __nv_bfloat16 g_vtl[(size_t)B_*H_*DH_*N_];

// unnormalized E = exp(S/8), bf16 hi/lo
__device__ __nv_bfloat16 g_pbh[(size_t)B_*H_*N_*N_];
__device__ __nv_bfloat16 g_pbl[(size_t)B_*H_*N_*N_];

// ---------------------------------------------------------------------------
// Helpers
// ---------------------------------------------------------------------------
__device__ __forceinline__ uint32_t smem_u32(const void* p) {
    uint32_t a;
    asm("{ .reg .u64 t; cvta.to.shared.u64 t, %1; cvt.u32.u64 %0, t; }"
        : "=r"(a) : "l"(p));
    return a;
}

#define LDM4(r, addr)                                                         \
    asm volatile("ldmatrix.sync.aligned.m8n8.x4.shared.b16 {%0,%1,%2,%3}, [%4];" \
        : "=r"((r)[0]), "=r"((r)[1]), "=r"((r)[2]), "=r"((r)[3])              \
        : "r"(addr))

#define MMA_BF16(c, a, b0, b1)                                                \
    asm volatile("mma.sync.aligned.m16n8k16.row.col.f32.bf16.bf16.f32 "       \
        "{%0,%1,%2,%3}, {%4,%5,%6,%7}, {%8,%9}, {%0,%1,%2,%3};"               \
        : "+f"((c)[0]), "+f"((c)[1]), "+f"((c)[2]), "+f"((c)[3])              \
        : "r"((a)[0]), "r"((a)[1]), "r"((a)[2]), "r"((a)[3]), "r"(b0), "r"(b1))

#define CP16(dst, src)                                                        \
    asm volatile("cp.async.cg.shared.global [%0], [%1], 16;"                  \
        :: "r"(dst), "l"(src))
#define CP_COMMIT() asm volatile("cp.async.commit_group;" ::: "memory")
#define CP_WAIT0()  asm volatile("cp.async.wait_group 0;" ::: "memory")
#define CP_WAIT1()  asm volatile("cp.async.wait_group 1;" ::: "memory")

__device__ __forceinline__ void bf_split(float v, __nv_bfloat16& h, __nv_bfloat16& l) {
    h = __float2bfloat16(v);
    l = __float2bfloat16(v - __bfloat162float(h));
}

__device__ __forceinline__ uint32_t bf_pack(__nv_bfloat16 a, __nv_bfloat16 b) {
    __nv_bfloat162 t(a, b);
    return *reinterpret_cast<uint32_t*>(&t);
}

// Fast exp on FMA pipes (validated R8-R13)
__device__ __forceinline__ float exp_fast(float x) {
    float y = x * 1.4426950408889634f;
    float nf = rintf(y);
    int   ni = (int)nf;
    float f = y - nf;
    float p = 1.5403530393e-4f;
    p = fmaf(p, f, 1.3333558146e-3f);
    p = fmaf(p, f, 9.6181291076e-3f);
    p = fmaf(p, f, 5.5504108664e-2f);
    p = fmaf(p, f, 2.4022650696e-1f);
    p = fmaf(p, f, 6.9314718246e-1f);
    p = fmaf(p, f, 1.0f);
    return p * __int_as_float((ni + 127) << 23);
}

// 64 B-row XOR-unit swizzle (validated R13): byte offset of 16B unit u, row r
#define GP_OFF(r, u) ((uint32_t)((r) * 64 + (((u) ^ (((r) >> 1) & 3)) << 4)))

// ---------------------------------------------------------------------------
// Fused split kernel (unchanged)
// ---------------------------------------------------------------------------
#define XBLK (M_ * D_ / 256)
#define WQBLK (J3_ * D_ / 256)
#define WPBLK (D_ * D_ / 256)

__global__ __launch_bounds__(256) void split_all(
    const float* __restrict__ x, const float* __restrict__ Wqkv,
    const float* __restrict__ Wproj,
    __nv_bfloat16* __restrict__ xhi, __nv_bfloat16* __restrict__ xlo,
    __nv_bfloat16* __restrict__ wqhi, __nv_bfloat16* __restrict__ wqlo,
    __nv_bfloat16* __restrict__ wphi, __nv_bfloat16* __restrict__ wplo)
{
    int blk = blockIdx.x;
    if (blk < XBLK) {
        int i = blk * 256 + threadIdx.x;
        float v = x[i];
        __nv_bfloat16 h, l; bf_split(v, h, l);
        xhi[i] = h; xlo[i] = l;
    } else if (blk < XBLK + WQBLK) {
        int idx = (blk - XBLK) * 256 + threadIdx.x;
        int j = idx >> 10, d = idx & 1023;
        int h = j / E3_, e = j % E3_;
        float v = Wqkv[((size_t)h * D_ + d) * E3_ + e];
        __nv_bfloat16 vh, vl; bf_split(v, vh, vl);
        wqhi[idx] = vh; wqlo[idx] = vl;
    } else {
        int i = (blk - XBLK - WQBLK) * 256 + threadIdx.x;
        float v = Wproj[i];
        __nv_bfloat16 h, l; bf_split(v, h, l);
        wphi[i] = h; wplo[i] = l;
    }
}

// ---------------------------------------------------------------------------
// gemm_pipe (unchanged from R13 — validated 3-stage)
// ---------------------------------------------------------------------------
#define GP_AH 0
#define GP_AL 8192
#define GP_BH 16384
#define GP_BL 24576
#define GP_STAGE 32768
#define GP_SMEM (3 * GP_STAGE)

template<int MODE>
__global__ __launch_bounds__(256) void gemm_pipe(
    const __nv_bfloat16* __restrict__ Ahi, const __nv_bfloat16* __restrict__ Alo,
    const __nv_bfloat16* __restrict__ Bhi, const __nv_bfloat16* __restrict__ Blo,
    const float* __restrict__ bias,
    float* __restrict__ oF,
    __nv_bfloat16* __restrict__ okh, __nv_bfloat16* __restrict__ okl,
    __nv_bfloat16* __restrict__ oqh, __nv_bfloat16* __restrict__ oql,
    __nv_bfloat16* __restrict__ ovh, __nv_bfloat16* __restrict__ ovl)
{
    extern __shared__ __nv_bfloat16 smem[];
    const uint32_t sb0 = smem_u32(smem);
    const int tid  = threadIdx.x;
    const int lane = tid & 31;
    const int wid  = tid >> 5;
    const int wm   = wid >> 2;
    const int wn   = wid & 3;
    const int m0 = blockIdx.x * 128;
    const int n0 = blockIdx.y * 128;

    float acc[4][4][4] = {};

    const int a_row  = wm * 64 + (lane & 15);
    const int a_half = lane >> 4;
    const int b_row  = wn * 32 + (lane & 7) + ((lane & 16) >> 1);
    const int b_half = (lane & 8) >> 3;

    const int lr0 = tid >> 2, lc0 = tid & 3;
    const int lr1 = lr0 + 64;

    auto load_chunk = [&](int kc, int st) {
        const uint32_t sbs = sb0 + st * GP_STAGE;
        const uint32_t so0 = GP_OFF(lr0, lc0);
        const uint32_t so1 = GP_OFF(lr1, lc0);
        size_t ga0 = (size_t)(m0 + lr0) * D_ + kc * 32 + lc0 * 8;
        size_t ga1 = (size_t)(m0 + lr1) * D_ + kc * 32 + lc0 * 8;
        size_t gb0 = (size_t)(n0 + lr0) * D_ + kc * 32 + lc0 * 8;
        size_t gb1 = (size_t)(n0 + lr1) * D_ + kc * 32 + lc0 * 8;
        CP16(sbs + GP_AH + so0, Ahi + ga0);
        CP16(sbs + GP_AH + so1, Ahi + ga1);
        CP16(sbs + GP_AL + so0, Alo + ga0);
        CP16(sbs + GP_AL + so1, Alo + ga1);
        CP16(sbs + GP_BH + so0, Bhi + gb0);
        CP16(sbs + GP_BH + so1, Bhi + gb1);
        CP16(sbs + GP_BL + so0, Blo + gb0);
        CP16(sbs + GP_BL + so1, Blo + gb1);
    };

    load_chunk(0, 0);
    CP_COMMIT();
    load_chunk(1, 1);
    CP_COMMIT();

    int st_cur = 0, st_next = 2;
    for (int kc = 0; kc < 32; kc++) {
        if (kc + 2 < 32) CP_WAIT1();
        else             CP_WAIT0();
        __syncthreads();
        if (kc + 2 < 32) {
            load_chunk(kc + 2, st_next);
            CP_COMMIT();
        }

        const uint32_t sbs = sb0 + st_cur * GP_STAGE;
        const uint32_t s_ah = sbs + GP_AH, s_al = sbs + GP_AL;
        const uint32_t s_bh = sbs + GP_BH, s_bl = sbs + GP_BL;

        #pragma unroll
        for (int kk = 0; kk < 2; kk++) {
            uint32_t bhf[2][4], blf[2][4];
            #pragma unroll
            for (int g = 0; g < 2; g++) {
                int br = b_row + g * 16;
                uint32_t ba = GP_OFF(br, kk * 2 + b_half);
                LDM4(bhf[g], s_bh + ba);
                LDM4(blf[g], s_bl + ba);
            }
            #pragma unroll
            for (int mp = 0; mp < 2; mp++) {
                uint32_t ahf[2][4], alf[2][4];
                #pragma unroll
                for (int i = 0; i < 2; i++) {
                    int ar = a_row + (mp * 2 + i) * 16;
                    uint32_t aa = GP_OFF(ar, kk * 2 + a_half);
                    LDM4(ahf[i], s_ah + aa);
                    LDM4(alf[i], s_al + aa);
                }
                #pragma unroll
                for (int i = 0; i < 2; i++)
                    #pragma unroll
                    for (int nt = 0; nt < 4; nt++)
                        MMA_BF16(acc[mp*2+i][nt], ahf[i], bhf[nt>>1][(nt&1)*2], bhf[nt>>1][(nt&1)*2+1]);
                #pragma unroll
                for (int i = 0; i < 2; i++)
                    #pragma unroll
                    for (int nt = 0; nt < 4; nt++)
                        MMA_BF16(acc[mp*2+i][nt], ahf[i], blf[nt>>1][(nt&1)*2], blf[nt>>1][(nt&1)*2+1]);
                #pragma unroll
                for (int i = 0; i < 2; i++)
                    #pragma unroll
                    for (int nt = 0; nt < 4; nt++)
                        MMA_BF16(acc[mp*2+i][nt], alf[i], bhf[nt>>1][(nt&1)*2], bhf[nt>>1][(nt&1)*2+1]);
            }
        }

        st_cur  = (st_cur  == 2) ? 0 : st_cur + 1;
        st_next = (st_next == 2) ? 0 : st_next + 1;
    }

    const int row0 = wm * 64 + (lane >> 2);
    const int col0 = wn * 32 + (lane & 3) * 2;
    #pragma unroll
    for (int mt = 0; mt < 4; mt++) {
        #pragma unroll
        for (int nt = 0; nt < 4; nt++) {
            #pragma unroll
            for (int r = 0; r < 4; r++) {
                int m = m0 + row0 + mt * 16 + (r >> 1) * 8;
                int j = n0 + col0 + nt * 8 + (r & 1);
                float val = acc[mt][nt][r] + bias[j];
                if (MODE == 1) {
                    oF[(size_t)m * D_ + j] = val;
                } else {
                    int b = m >> 11, n = m & (N_ - 1);
                    int h = j / E3_, e = j % E3_;
                    __nv_bfloat16 vh, vl; bf_split(val, vh, vl);
                    if (e < DH_) {
                        size_t o = ((size_t)(b * H_ + h) * N_ + n) * DH_ + e;
                        okh[o] = vh; okl[o] = vl;
                    } else if (e < 2 * DH_) {
                        size_t o = ((size_t)(b * H_ + h) * N_ + n) * DH_ + (e - DH_);
                        oqh[o] = vh; oql[o] = vl;
                    } else {
                        size_t o = ((size_t)(b * H_ + h) * DH_ + (e - 2 * DH_)) * N_ + n;
                        ovh[o] = vh; ovl[o] = vl;
                    }
                }
            }
        }
    }
}

// ---------------------------------------------------------------------------
// scores_exp (unchanged from R10/R13)
// ---------------------------------------------------------------------------
#define SC_LDS 72
#define SC_TILE (128 * SC_LDS)
#define SC_AH 0
#define SC_AL (1 * SC_TILE)
#define SC_BH (2 * SC_TILE)
#define SC_BL (3 * SC_TILE)
#define SC_PS_OFF (4 * SC_TILE * 2)
#define SC_SMEM (4 * SC_TILE * 2 + 2048)

__global__ __launch_bounds__(256) void scores_exp(
    const __nv_bfloat16* __restrict__ Qh, const __nv_bfloat16* __restrict__ Ql,
    const __nv_bfloat16* __restrict__ Kh, const __nv_bfloat16* __restrict__ Kl,
    __nv_bfloat16* __restrict__ pbh, __nv_bfloat16* __restrict__ pbl,
    float* __restrict__ psum)
{
    const int qt = blockIdx.x, kt = blockIdx.y, bh = blockIdx.z;
    if (kt > qt) return;

    extern __shared__ __nv_bfloat16 smem[];
    const uint32_t sb0 = smem_u32(smem);
    float* psum_s = (float*)((char*)smem + SC_PS_OFF);
    const int tid  = threadIdx.x;
    const int lane = tid & 31;
    const int wid  = tid >> 5;
    const int wm   = wid >> 2;
    const int wn   = wid & 3;

    const uint32_t s_ah = sb0 + SC_AH * 2;
    const uint32_t s_al = sb0 + SC_AL * 2;
    const uint32_t s_bh = sb0 + SC_BH * 2;
    const uint32_t s_bl = sb0 + SC_BL * 2;

    const __nv_bfloat16* qhb = Qh + ((size_t)bh * N_ + qt * 128) * DH_;
    const __nv_bfloat16* qlb = Ql + ((size_t)bh * N_ + qt * 128) * DH_;
    const __nv_bfloat16* khb = Kh + ((size_t)bh * N_ + kt * 128) * DH_;
    const __nv_bfloat16* klb = Kl + ((size_t)bh * N_ + kt * 128) * DH_;

    #pragma unroll
    for (int i = 0; i < 4; i++) {
        int u  = tid + i * 256;
        int r  = u >> 3, c8 = u & 7;
        uint32_t so = (uint32_t)(r * SC_LDS + c8 * 8) * 2;
        size_t g = (size_t)r * DH_ + c8 * 8;
        CP16(s_ah + so, qhb + g);
        CP16(s_al + so, qlb + g);
        CP16(s_bh + so, khb + g);
        CP16(s_bl + so, klb + g);
    }
    CP_COMMIT();
    CP_WAIT0();
    __syncthreads();

    const uint32_t a_row  = (uint32_t)(wm * 64 + (lane & 15));
    const uint32_t a_coff = (uint32_t)(((lane >> 4) << 3) * 2);
    const uint32_t b_row  = (uint32_t)(wn * 32 + (lane & 7) + ((lane & 16) >> 1));
    const uint32_t b_coff = (uint32_t)((lane & 8) * 2);

    float acc[4][4][4] = {};
    #pragma unroll
    for (int kk = 0; kk < 4; kk++) {
        const uint32_t kb = (uint32_t)(kk * 16 * 2);
        uint32_t bhf[2][4], blf[2][4];
        #pragma unroll
        for (int g = 0; g < 2; g++) {
            uint32_t ba = (b_row + g * 16) * (SC_LDS * 2) + kb + b_coff;
            LDM4(bhf[g], s_bh + ba);
            LDM4(blf[g], s_bl + ba);
        }
        #pragma unroll
        for (int mp = 0; mp < 2; mp++) {
            uint32_t ahf[2][4], alf[2][4];
            #pragma unroll
            for (int i = 0; i < 2; i++) {
                uint32_t aa = (a_row + (mp * 2 + i) * 16) * (SC_LDS * 2) + kb + a_coff;
                LDM4(ahf[i], s_ah + aa);
                LDM4(alf[i], s_al + aa);
            }
            #pragma unroll
            for (int i = 0; i < 2; i++)
                #pragma unroll
                for (int nt = 0; nt < 4; nt++)
                    MMA_BF16(acc[mp*2+i][nt], ahf[i], bhf[nt>>1][(nt&1)*2], bhf[nt>>1][(nt&1)*2+1]);
            #pragma unroll
            for (int i = 0; i < 2; i++)
                #pragma unroll
                for (int nt = 0; nt < 4; nt++)
                    MMA_BF16(acc[mp*2+i][nt], ahf[i], blf[nt>>1][(nt&1)*2], blf[nt>>1][(nt&1)*2+1]);
            #pragma unroll
            for (int i = 0; i < 2; i++)
                #pragma unroll
                for (int nt = 0; nt < 4; nt++)
                    MMA_BF16(acc[mp*2+i][nt], alf[i], bhf[nt>>1][(nt&1)*2], bhf[nt>>1][(nt&1)*2+1]);
        }
    }

    __nv_bfloat16* ph_b = pbh + (size_t)bh * N_ * N_;
    __nv_bfloat16* pl_b = pbl + (size_t)bh * N_ * N_;
    const int rbase_l = wm * 64 + (lane >> 2);
    const int cbase   = wn * 32 + (lane & 3) * 2;
    const bool diag = (kt == qt);

    #pragma unroll
    for (int mt = 0; mt < 4; mt++) {
        #pragma unroll
        for (int rh = 0; rh < 2; rh++) {
            const int row_l = rbase_l + mt * 16 + rh * 8;
            const int row_g = qt * 128 + row_l;
            __nv_bfloat16* phrow = ph_b + (size_t)row_g * N_;
            __nv_bfloat16* plrow = pl_b + (size_t)row_g * N_;
            float s = 0.f;
            #pragma unroll
            for (int nt = 0; nt < 4; nt++) {
                int c = kt * 128 + cbase + nt * 8;
                float e0 = exp_fast(acc[mt][nt][rh * 2 + 0] * 0.125f);
                float e1 = exp_fast(acc[mt][nt][rh * 2 + 1] * 0.125f);
                if (diag) {
                    if (c > row_g)     e0 = 0.f;
                    if (c + 1 > row_g) e1 = 0.f;
                }
                s += e0 + e1;
                __nv_bfloat16 h0, l0, h1, l1;
                bf_split(e0, h0, l0);
                bf_split(e1, h1, l1);
                *(uint32_t*)(phrow + c) = bf_pack(h0, h1);
                *(uint32_t*)(plrow + c) = bf_pack(l0, l1);
            }
            s += __shfl_xor_sync(~0u, s, 1);
            s += __shfl_xor_sync(~0u, s, 2);
            if ((lane & 3) == 0)
                psum_s[wn * 128 + row_l] = s;
        }
    }
    __syncthreads();
    if (tid < 128) {
        float s = psum_s[tid] + psum_s[128 + tid] + psum_s[256 + tid] + psum_s[384 + tid];
        psum[(((size_t)bh * N_) + qt * 128 + tid) * 16 + kt] = s;
    }
}

// ---------------------------------------------------------------------------
// finalize_inv (unchanged)
// ---------------------------------------------------------------------------
__global__ __launch_bounds__(256) void finalize_inv(
    const float* __restrict__ psum, float* __restrict__ ginv)
{
    int r = blockIdx.x * 256 + threadIdx.x;
    int row = r & (N_ - 1);
    int ktmax = row >> 7;
    const float* p = psum + (size_t)r * 16;
    float s = 0.f;
    for (int kt = 0; kt <= ktmax; kt++) s += p[kt];
    ginv[r] = 1.0f / s;
}

// ---------------------------------------------------------------------------
// attn_write (unchanged from R10)
// ---------------------------------------------------------------------------
__global__ __launch_bounds__(256) void attn_write(
    const __nv_bfloat16* __restrict__ pbh, const __nv_bfloat16* __restrict__ pbl,
    const float* __restrict__ ginv, float* __restrict__ attn)
{
    const size_t r = blockIdx.x;
    const int row = blockIdx.x & (N_ - 1);
    const int kmax = ((row >> 7) + 1) << 7;
    const float iv = ginv[r];
    const __nv_bfloat16* phrow = pbh + r * N_;
    const __nv_bfloat16* plrow = pbl + r * N_;
    float* arow = attn + r * N_;
    const int tid = threadIdx.x;

    for (int c = tid * 4; c < kmax; c += 1024) {
        uint2 uh = *(const uint2*)(phrow + c);
        uint2 ul = *(const uint2*)(plrow + c);
        __nv_bfloat162 h01 = *reinterpret_cast<__nv_bfloat162*>(&uh.x);
        __nv_bfloat162 h23 = *reinterpret_cast<__nv_bfloat162*>(&uh.y);
        __nv_bfloat162 l01 = *reinterpret_cast<__nv_bfloat162*>(&ul.x);
        __nv_bfloat162 l23 = *reinterpret_cast<__nv_bfloat162*>(&ul.y);
        float4 o;
        o.x = (__bfloat162float(h01.x) + __bfloat162float(l01.x)) * iv;
        o.y = (__bfloat162float(h01.y) + __bfloat162float(l01.y)) * iv;
        o.z = (__bfloat162float(h23.x) + __bfloat162float(l23.x)) * iv;
        o.w = (__bfloat162float(h23.y) + __bfloat162float(l23.y)) * iv;
        *(float4*)(arow + c) = o;
    }
    const float4 z4 = make_float4(0.f, 0.f, 0.f, 0.f);
    for (int c = kmax + tid * 4; c < N_; c += 1024)
        *(float4*)(arow + c) = z4;
}

// ---------------------------------------------------------------------------
// sa_pipe: 3-stage cp.async pipeline (R13-validated scheme), chunk 32 cols.
// 64 B row stride + GP_OFF swizzle. Stage = P 16KB + V 8KB = 24,576 B;
// 3 stages x 2 CTAs = 147 KB total smem per SM -> 2 CTAs preserved.
// sa = (E @ V) * inv[row] in epilogue.
// ---------------------------------------------------------------------------
#define SP_PH 0
#define SP_PL 8192
#define SP_VH 16384
#define SP_VL 20480
#define SP_STAGE 24576
#define SP_SMEM (3 * SP_STAGE)          // 73,728 B

__global__ __launch_bounds__(256) void sa_pipe(
    const __nv_bfloat16* __restrict__ Ph, const __nv_bfloat16* __restrict__ Pl,
    const __nv_bfloat16* __restrict__ Vth, const __nv_bfloat16* __restrict__ Vtl,
    const float* __restrict__ ginv,
    __nv_bfloat16* __restrict__ sahi, __nv_bfloat16* __restrict__ salo)
{
    extern __shared__ __nv_bfloat16 smem[];
    const uint32_t sb0 = smem_u32(smem);
    const int bh = blockIdx.x;
    const int qt = (N_ / 128 - 1) - blockIdx.y;
    const int tid  = threadIdx.x;
    const int lane = tid & 31;
    const int wid  = tid >> 5;
    const int wm   = wid >> 2;
    const int wn   = wid & 3;

    const __nv_bfloat16* phb = Ph + ((size_t)bh * N_ + qt * 128) * N_;
    const __nv_bfloat16* plb = Pl + ((size_t)bh * N_ + qt * 128) * N_;
    const __nv_bfloat16* vhb = Vth + (size_t)bh * DH_ * N_;
    const __nv_bfloat16* vlb = Vtl + (size_t)bh * DH_ * N_;

    float acc[4][2][4] = {};

    const int a_row  = wm * 64 + (lane & 15);
    const int a_half = lane >> 4;
    const int b_row  = wn * 16 + (lane & 7) + ((lane & 16) >> 1);
    const int b_half = (lane & 8) >> 3;

    // load mapping: P has 512 16B-units/chunk (2/thread), V has 256 (1/thread)
    const int plr0 = tid >> 2, plc = tid & 3;      // P row 0..63, unit
    const int plr1 = plr0 + 64;                    // P row 64..127
    const int vlr  = tid >> 2;                     // V row 0..63 (tid<256 -> all rows)

    auto load_chunk = [&](int kc, int st) {
        const uint32_t sbs = sb0 + st * SP_STAGE;
        const int kofs = kc * 32;
        {
            const uint32_t so0 = GP_OFF(plr0, plc);
            const uint32_t so1 = GP_OFF(plr1, plc);
            size_t g0 = (size_t)plr0 * N_ + kofs + plc * 8;
            size_t g1 = (size_t)plr1 * N_ + kofs + plc * 8;
            CP16(sbs + SP_PH + so0, phb + g0);
            CP16(sbs + SP_PH + so1, phb + g1);
            CP16(sbs + SP_PL + so0, plb + g0);
            CP16(sbs + SP_PL + so1, plb + g1);
        }
        {
            const uint32_t so = GP_OFF(vlr, plc);
            size_t g = (size_t)vlr * N_ + kofs + plc * 8;
            CP16(sbs + SP_VH + so, vhb + g);
            CP16(sbs + SP_VL + so, vlb + g);
        }
    };

    const int nchunks = (qt + 1) * 4;
    load_chunk(0, 0);
    CP_COMMIT();
    load_chunk(1, 1);
    CP_COMMIT();

    int st_cur = 0, st_next = 2;
    for (int kc = 0; kc < nchunks; kc++) {
        if (kc + 2 < nchunks) CP_WAIT1();
        else                  CP_WAIT0();
        __syncthreads();
        if (kc + 2 < nchunks) {
            load_chunk(kc + 2, st_next);
            CP_COMMIT();
        }

        const uint32_t sbs = sb0 + st_cur * SP_STAGE;
        const uint32_t s_ph = sbs + SP_PH, s_pl = sbs + SP_PL;
        const uint32_t s_vh = sbs + SP_VH, s_vl = sbs + SP_VL;

        #pragma unroll
        for (int kk = 0; kk < 2; kk++) {
            uint32_t bhf[4], blf[4];
            uint32_t ba = GP_OFF(b_row, kk * 2 + b_half);
            LDM4(bhf, s_vh + ba);
            LDM4(blf, s_vl + ba);
            uint32_t ahf[4][4], alf[4][4];
            #pragma unroll
            for (int mt = 0; mt < 4; mt++) {
                uint32_t aa = GP_OFF(a_row + mt * 16, kk * 2 + a_half);
                LDM4(ahf[mt], s_ph + aa);
                LDM4(alf[mt], s_pl + aa);
            }
            #pragma unroll
            for (int mt = 0; mt < 4; mt++)
                #pragma unroll
                for (int nt = 0; nt < 2; nt++)
                    MMA_BF16(acc[mt][nt], ahf[mt], bhf[nt*2], bhf[nt*2+1]);
            #pragma unroll
            for (int mt = 0; mt < 4; mt++)
                #pragma unroll
                for (int nt = 0; nt < 2; nt++)
                    MMA_BF16(acc[mt][nt], ahf[mt], blf[nt*2], blf[nt*2+1]);
            #pragma unroll
            for (int mt = 0; mt < 4; mt++)
                #pragma unroll
                for (int nt = 0; nt < 2; nt++)
                    MMA_BF16(acc[mt][nt], alf[mt], bhf[nt*2], bhf[nt*2+1]);
        }

        st_cur  = (st_cur  == 2) ? 0 : st_cur + 1;
        st_next = (st_next == 2) ? 0 : st_next + 1;
    }

    const int b = bh >> 4, h = bh & 15;
    const int row0 = wm * 64 + (lane >> 2);
    const int col0 = wn * 16 + (lane & 3) * 2;
    const float* inv_b = ginv + (size_t)bh * N_;

    float ivr[8];
    #pragma unroll
    for (int mt = 0; mt < 4; mt++)
        #pragma unroll
        for (int rh = 0; rh < 2; rh++)
            ivr[mt * 2 + rh] = inv_b[qt * 128 + row0 + mt * 16 + rh * 8];

    #pragma unroll
    for (int mt = 0; mt < 4; mt++) {
        #pragma unroll
        for (int nt = 0; nt < 2; nt++) {
            #pragma unroll
            for (int r = 0; r < 4; r++) {
                int n  = qt * 128 + row0 + mt * 16 + (r >> 1) * 8;
                int dh = col0 + nt * 8 + (r & 1);
                size_t o = ((size_t)b * N_ + n) * D_ + h * DH_ + dh;
                __nv_bfloat16 vh, vl;
                bf_split(acc[mt][nt][r] * ivr[mt * 2 + (r >> 1)], vh, vl);
                sahi[o] = vh; salo[o] = vl;
            }
        }
    }
}

// ---------------------------------------------------------------------------
extern "C" void kernel_launch(void* const* d_in, const int* in_sizes, int n_in,
                              void* d_out, int out_size)
{
    const float* x     = (const float*)d_in[0];
    const float* Wqkv  = (const float*)d_in[1];
    const float* bqkv  = (const float*)d_in[2];
    const float* Wproj = (const float*)d_in[3];
    const float* bproj = (const float*)d_in[4];
    float* out = (float*)d_out;

    const size_t OUT_ELEMS  = (size_t)B_ * N_ * D_;
    const size_t ATTN_ELEMS = (size_t)B_ * H_ * N_ * N_;

    float* attnp;
    cudaGetSymbolAddress((void**)&attnp, g_attn);
    if ((size_t)out_size >= OUT_ELEMS + ATTN_ELEMS)
        attnp = out + OUT_ELEMS;

    float *ginv, *psum;
    cudaGetSymbolAddress((void**)&ginv, g_inv);
    cudaGetSymbolAddress((void**)&psum, g_psum);

    __nv_bfloat16 *xhi, *xlo, *wqhi, *wqlo, *wphi, *wplo, *sahi, *salo;
    __nv_bfloat16 *qh, *ql, *kh, *kl, *vth, *vtl, *pbh, *pbl;
    cudaGetSymbolAddress((void**)&xhi,  g_xhi);
    cudaGetSymbolAddress((void**)&xlo,  g_xlo);
    cudaGetSymbolAddress((void**)&wqhi, g_wqhi);
    cudaGetSymbolAddress((void**)&wqlo, g_wqlo);
    cudaGetSymbolAddress((void**)&wphi, g_wphi);
    cudaGetSymbolAddress((void**)&wplo, g_wplo);
    cudaGetSymbolAddress((void**)&sahi, g_sahi);
    cudaGetSymbolAddress((void**)&salo, g_salo);
    cudaGetSymbolAddress((void**)&qh,   g_qh);
    cudaGetSymbolAddress((void**)&ql,   g_ql);
    cudaGetSymbolAddress((void**)&kh,   g_kh);
    cudaGetSymbolAddress((void**)&kl,   g_kl);
    cudaGetSymbolAddress((void**)&vth,  g_vth);
    cudaGetSymbolAddress((void**)&vtl,  g_vtl);
    cudaGetSymbolAddress((void**)&pbh,  g_pbh);
    cudaGetSymbolAddress((void**)&pbl,  g_pbl);

    cudaFuncSetAttribute(gemm_pipe<0>, cudaFuncAttributeMaxDynamicSharedMemorySize, GP_SMEM);
    cudaFuncSetAttribute(gemm_pipe<1>, cudaFuncAttributeMaxDynamicSharedMemorySize, GP_SMEM);
    cudaFuncSetAttribute(scores_exp,   cudaFuncAttributeMaxDynamicSharedMemorySize, SC_SMEM);
    cudaFuncSetAttribute(sa_pipe,      cudaFuncAttributeMaxDynamicSharedMemorySize, SP_SMEM);

    split_all<<<XBLK + WQBLK + WPBLK, 256>>>(
        x, Wqkv, Wproj, xhi, xlo, wqhi, wqlo, wphi, wplo);

    gemm_pipe<0><<<dim3(M_ / 128, J3_ / 128), 256, GP_SMEM>>>(
        xhi, xlo, wqhi, wqlo, bqkv, nullptr, kh, kl, qh, ql, vth, vtl);

    scores_exp<<<dim3(N_ / 128, N_ / 128, B_ * H_), 256, SC_SMEM>>>(
        qh, ql, kh, kl, pbh, pbl, psum);

    finalize_inv<<<(B_ * H_ * N_) / 256, 256>>>(psum, ginv);

    attn_write<<<B_ * H_ * N_, 256>>>(pbh, pbl, ginv, attnp);

    sa_pipe<<<dim3(B_ * H_, N_ / 128), 256, SP_SMEM>>>(
        pbh, pbl, vth, vtl, ginv, sahi, salo);

    gemm_pipe<1><<<dim3(M_ / 128, D_ / 128), 256, GP_SMEM>>>(
        sahi, salo, wphi, wplo, bproj, out,
        nullptr, nullptr, nullptr, nullptr, nullptr, nullptr);
}

// round 15
// speedup vs baseline: 1.0225x; 1.0225x over previous
#include <cuda_runtime.h>
#include <cuda_bf16.h>
#include <math.h>
#include <stdint.h>

// Problem constants
#define B_  2
#define N_  2048
#define D_  1024
#define H_  16
#define DH_ 64
#define E3_ 192
#define J3_ 3072
#define M_  4096

// ---------------------------------------------------------------------------
// Scratch (device globals)
// ---------------------------------------------------------------------------
__device__ float g_attn[(size_t)B_*H_*N_*N_];
__device__ float g_inv [(size_t)B_*H_*N_];
__device__ float g_psum[(size_t)B_*H_*N_*16];

__device__ __nv_bfloat16 g_xhi [(size_t)M_*D_];
__device__ __nv_bfloat16 g_xlo [(size_t)M_*D_];
__device__ __nv_bfloat16 g_wqhi[(size_t)J3_*D_];
__device__ __nv_bfloat16 g_wqlo[(size_t)J3_*D_];
__device__ __nv_bfloat16 g_wphi[(size_t)D_*D_];
__device__ __nv_bfloat16 g_wplo[(size_t)D_*D_];
__device__ __nv_bfloat16 g_sahi[(size_t)M_*D_];
__device__ __nv_bfloat16 g_salo[(size_t)M_*D_];

__device__ __nv_bfloat16 g_qh[(size_t)B_*H_*N_*DH_];
__device__ __nv_bfloat16 g_ql[(size_t)B_*H_*N_*DH_];
__device__ __nv_bfloat16 g_kh[(size_t)B_*H_*N_*DH_];
__device__ __nv_bfloat16 g_kl[(size_t)B_*H_*N_*DH_];
__device__ __nv_bfloat16 g_vth[(size_t)B_*H_*DH_*N_];
__device__ __nv_bfloat16 g_vtl[(size_t)B_*H_*DH_*N_];

__device__ __nv_bfloat16 g_pbh[(size_t)B_*H_*N_*N_];
__device__ __nv_bfloat16 g_pbl[(size_t)B_*H_*N_*N_];

// ---------------------------------------------------------------------------
// Helpers
// ---------------------------------------------------------------------------
__device__ __forceinline__ uint32_t smem_u32(const void* p) {
    uint32_t a;
    asm("{ .reg .u64 t; cvta.to.shared.u64 t, %1; cvt.u32.u64 %0, t; }"
        : "=r"(a) : "l"(p));
    return a;
}

#define LDM4(r, addr)                                                         \
    asm volatile("ldmatrix.sync.aligned.m8n8.x4.shared.b16 {%0,%1,%2,%3}, [%4];" \
        : "=r"((r)[0]), "=r"((r)[1]), "=r"((r)[2]), "=r"((r)[3])              \
        : "r"(addr))

#define MMA_BF16(c, a, b0, b1)                                                \
    asm volatile("mma.sync.aligned.m16n8k16.row.col.f32.bf16.bf16.f32 "       \
        "{%0,%1,%2,%3}, {%4,%5,%6,%7}, {%8,%9}, {%0,%1,%2,%3};"               \
        : "+f"((c)[0]), "+f"((c)[1]), "+f"((c)[2]), "+f"((c)[3])              \
        : "r"((a)[0]), "r"((a)[1]), "r"((a)[2]), "r"((a)[3]), "r"(b0), "r"(b1))

#define CP16(dst, src)                                                        \
    asm volatile("cp.async.cg.shared.global [%0], [%1], 16;"                  \
        :: "r"(dst), "l"(src))
#define CP_COMMIT() asm volatile("cp.async.commit_group;" ::: "memory")
#define CP_WAIT0()  asm volatile("cp.async.wait_group 0;" ::: "memory")
#define CP_WAIT1()  asm volatile("cp.async.wait_group 1;" ::: "memory")

__device__ __forceinline__ void bf_split(float v, __nv_bfloat16& h, __nv_bfloat16& l) {
    h = __float2bfloat16(v);
    l = __float2bfloat16(v - __bfloat162float(h));
}

__device__ __forceinline__ uint32_t bf_pack(__nv_bfloat16 a, __nv_bfloat16 b) {
    __nv_bfloat162 t(a, b);
    return *reinterpret_cast<uint32_t*>(&t);
}

// Fast exp on FMA pipes (validated R8-R13)
__device__ __forceinline__ float exp_fast(float x) {
    float y = x * 1.4426950408889634f;
    float nf = rintf(y);
    int   ni = (int)nf;
    float f = y - nf;
    float p = 1.5403530393e-4f;
    p = fmaf(p, f, 1.3333558146e-3f);
    p = fmaf(p, f, 9.6181291076e-3f);
    p = fmaf(p, f, 5.5504108664e-2f);
    p = fmaf(p, f, 2.4022650696e-1f);
    p = fmaf(p, f, 6.9314718246e-1f);
    p = fmaf(p, f, 1.0f);
    return p * __int_as_float((ni + 127) << 23);
}

// 64 B-row XOR-unit swizzle (validated R13)
#define GP_OFF(r, u) ((uint32_t)((r) * 64 + (((u) ^ (((r) >> 1) & 3)) << 4)))

// ---------------------------------------------------------------------------
// Fused split kernel (unchanged)
// ---------------------------------------------------------------------------
#define XBLK (M_ * D_ / 256)
#define WQBLK (J3_ * D_ / 256)
#define WPBLK (D_ * D_ / 256)

__global__ __launch_bounds__(256) void split_all(
    const float* __restrict__ x, const float* __restrict__ Wqkv,
    const float* __restrict__ Wproj,
    __nv_bfloat16* __restrict__ xhi, __nv_bfloat16* __restrict__ xlo,
    __nv_bfloat16* __restrict__ wqhi, __nv_bfloat16* __restrict__ wqlo,
    __nv_bfloat16* __restrict__ wphi, __nv_bfloat16* __restrict__ wplo)
{
    int blk = blockIdx.x;
    if (blk < XBLK) {
        int i = blk * 256 + threadIdx.x;
        float v = x[i];
        __nv_bfloat16 h, l; bf_split(v, h, l);
        xhi[i] = h; xlo[i] = l;
    } else if (blk < XBLK + WQBLK) {
        int idx = (blk - XBLK) * 256 + threadIdx.x;
        int j = idx >> 10, d = idx & 1023;
        int h = j / E3_, e = j % E3_;
        float v = Wqkv[((size_t)h * D_ + d) * E3_ + e];
        __nv_bfloat16 vh, vl; bf_split(v, vh, vl);
        wqhi[idx] = vh; wqlo[idx] = vl;
    } else {
        int i = (blk - XBLK - WQBLK) * 256 + threadIdx.x;
        float v = Wproj[i];
        __nv_bfloat16 h, l; bf_split(v, h, l);
        wphi[i] = h; wplo[i] = l;
    }
}

// ---------------------------------------------------------------------------
// gemm_pipe (unchanged from R13 — validated 3-stage)
// ---------------------------------------------------------------------------
#define GP_AH 0
#define GP_AL 8192
#define GP_BH 16384
#define GP_BL 24576
#define GP_STAGE 32768
#define GP_SMEM (3 * GP_STAGE)

template<int MODE>
__global__ __launch_bounds__(256) void gemm_pipe(
    const __nv_bfloat16* __restrict__ Ahi, const __nv_bfloat16* __restrict__ Alo,
    const __nv_bfloat16* __restrict__ Bhi, const __nv_bfloat16* __restrict__ Blo,
    const float* __restrict__ bias,
    float* __restrict__ oF,
    __nv_bfloat16* __restrict__ okh, __nv_bfloat16* __restrict__ okl,
    __nv_bfloat16* __restrict__ oqh, __nv_bfloat16* __restrict__ oql,
    __nv_bfloat16* __restrict__ ovh, __nv_bfloat16* __restrict__ ovl)
{
    extern __shared__ __nv_bfloat16 smem[];
    const uint32_t sb0 = smem_u32(smem);
    const int tid  = threadIdx.x;
    const int lane = tid & 31;
    const int wid  = tid >> 5;
    const int wm   = wid >> 2;
    const int wn   = wid & 3;
    const int m0 = blockIdx.x * 128;
    const int n0 = blockIdx.y * 128;

    float acc[4][4][4] = {};

    const int a_row  = wm * 64 + (lane & 15);
    const int a_half = lane >> 4;
    const int b_row  = wn * 32 + (lane & 7) + ((lane & 16) >> 1);
    const int b_half = (lane & 8) >> 3;

    const int lr0 = tid >> 2, lc0 = tid & 3;
    const int lr1 = lr0 + 64;

    auto load_chunk = [&](int kc, int st) {
        const uint32_t sbs = sb0 + st * GP_STAGE;
        const uint32_t so0 = GP_OFF(lr0, lc0);
        const uint32_t so1 = GP_OFF(lr1, lc0);
        size_t ga0 = (size_t)(m0 + lr0) * D_ + kc * 32 + lc0 * 8;
        size_t ga1 = (size_t)(m0 + lr1) * D_ + kc * 32 + lc0 * 8;
        size_t gb0 = (size_t)(n0 + lr0) * D_ + kc * 32 + lc0 * 8;
        size_t gb1 = (size_t)(n0 + lr1) * D_ + kc * 32 + lc0 * 8;
        CP16(sbs + GP_AH + so0, Ahi + ga0);
        CP16(sbs + GP_AH + so1, Ahi + ga1);
        CP16(sbs + GP_AL + so0, Alo + ga0);
        CP16(sbs + GP_AL + so1, Alo + ga1);
        CP16(sbs + GP_BH + so0, Bhi + gb0);
        CP16(sbs + GP_BH + so1, Bhi + gb1);
        CP16(sbs + GP_BL + so0, Blo + gb0);
        CP16(sbs + GP_BL + so1, Blo + gb1);
    };

    load_chunk(0, 0);
    CP_COMMIT();
    load_chunk(1, 1);
    CP_COMMIT();

    int st_cur = 0, st_next = 2;
    for (int kc = 0; kc < 32; kc++) {
        if (kc + 2 < 32) CP_WAIT1();
        else             CP_WAIT0();
        __syncthreads();
        if (kc + 2 < 32) {
            load_chunk(kc + 2, st_next);
            CP_COMMIT();
        }

        const uint32_t sbs = sb0 + st_cur * GP_STAGE;
        const uint32_t s_ah = sbs + GP_AH, s_al = sbs + GP_AL;
        const uint32_t s_bh = sbs + GP_BH, s_bl = sbs + GP_BL;

        #pragma unroll
        for (int kk = 0; kk < 2; kk++) {
            uint32_t bhf[2][4], blf[2][4];
            #pragma unroll
            for (int g = 0; g < 2; g++) {
                int br = b_row + g * 16;
                uint32_t ba = GP_OFF(br, kk * 2 + b_half);
                LDM4(bhf[g], s_bh + ba);
                LDM4(blf[g], s_bl + ba);
            }
            #pragma unroll
            for (int mp = 0; mp < 2; mp++) {
                uint32_t ahf[2][4], alf[2][4];
                #pragma unroll
                for (int i = 0; i < 2; i++) {
                    int ar = a_row + (mp * 2 + i) * 16;
                    uint32_t aa = GP_OFF(ar, kk * 2 + a_half);
                    LDM4(ahf[i], s_ah + aa);
                    LDM4(alf[i], s_al + aa);
                }
                #pragma unroll
                for (int i = 0; i < 2; i++)
                    #pragma unroll
                    for (int nt = 0; nt < 4; nt++)
                        MMA_BF16(acc[mp*2+i][nt], ahf[i], bhf[nt>>1][(nt&1)*2], bhf[nt>>1][(nt&1)*2+1]);
                #pragma unroll
                for (int i = 0; i < 2; i++)
                    #pragma unroll
                    for (int nt = 0; nt < 4; nt++)
                        MMA_BF16(acc[mp*2+i][nt], ahf[i], blf[nt>>1][(nt&1)*2], blf[nt>>1][(nt&1)*2+1]);
                #pragma unroll
                for (int i = 0; i < 2; i++)
                    #pragma unroll
                    for (int nt = 0; nt < 4; nt++)
                        MMA_BF16(acc[mp*2+i][nt], alf[i], bhf[nt>>1][(nt&1)*2], bhf[nt>>1][(nt&1)*2+1]);
            }
        }

        st_cur  = (st_cur  == 2) ? 0 : st_cur + 1;
        st_next = (st_next == 2) ? 0 : st_next + 1;
    }

    const int row0 = wm * 64 + (lane >> 2);
    const int col0 = wn * 32 + (lane & 3) * 2;
    #pragma unroll
    for (int mt = 0; mt < 4; mt++) {
        #pragma unroll
        for (int nt = 0; nt < 4; nt++) {
            #pragma unroll
            for (int r = 0; r < 4; r++) {
                int m = m0 + row0 + mt * 16 + (r >> 1) * 8;
                int j = n0 + col0 + nt * 8 + (r & 1);
                float val = acc[mt][nt][r] + bias[j];
                if (MODE == 1) {
                    oF[(size_t)m * D_ + j] = val;
                } else {
                    int b = m >> 11, n = m & (N_ - 1);
                    int h = j / E3_, e = j % E3_;
                    __nv_bfloat16 vh, vl; bf_split(val, vh, vl);
                    if (e < DH_) {
                        size_t o = ((size_t)(b * H_ + h) * N_ + n) * DH_ + e;
                        okh[o] = vh; okl[o] = vl;
                    } else if (e < 2 * DH_) {
                        size_t o = ((size_t)(b * H_ + h) * N_ + n) * DH_ + (e - DH_);
                        oqh[o] = vh; oql[o] = vl;
                    } else {
                        size_t o = ((size_t)(b * H_ + h) * DH_ + (e - 2 * DH_)) * N_ + n;
                        ovh[o] = vh; ovl[o] = vl;
                    }
                }
            }
        }
    }
}

// ---------------------------------------------------------------------------
// scores_exp (unchanged from R10/R13)
// ---------------------------------------------------------------------------
#define SC_LDS 72
#define SC_TILE (128 * SC_LDS)
#define SC_AH 0
#define SC_AL (1 * SC_TILE)
#define SC_BH (2 * SC_TILE)
#define SC_BL (3 * SC_TILE)
#define SC_PS_OFF (4 * SC_TILE * 2)
#define SC_SMEM (4 * SC_TILE * 2 + 2048)

__global__ __launch_bounds__(256) void scores_exp(
    const __nv_bfloat16* __restrict__ Qh, const __nv_bfloat16* __restrict__ Ql,
    const __nv_bfloat16* __restrict__ Kh, const __nv_bfloat16* __restrict__ Kl,
    __nv_bfloat16* __restrict__ pbh, __nv_bfloat16* __restrict__ pbl,
    float* __restrict__ psum)
{
    const int qt = blockIdx.x, kt = blockIdx.y, bh = blockIdx.z;
    if (kt > qt) return;

    extern __shared__ __nv_bfloat16 smem[];
    const uint32_t sb0 = smem_u32(smem);
    float* psum_s = (float*)((char*)smem + SC_PS_OFF);
    const int tid  = threadIdx.x;
    const int lane = tid & 31;
    const int wid  = tid >> 5;
    const int wm   = wid >> 2;
    const int wn   = wid & 3;

    const uint32_t s_ah = sb0 + SC_AH * 2;
    const uint32_t s_al = sb0 + SC_AL * 2;
    const uint32_t s_bh = sb0 + SC_BH * 2;
    const uint32_t s_bl = sb0 + SC_BL * 2;

    const __nv_bfloat16* qhb = Qh + ((size_t)bh * N_ + qt * 128) * DH_;
    const __nv_bfloat16* qlb = Ql + ((size_t)bh * N_ + qt * 128) * DH_;
    const __nv_bfloat16* khb = Kh + ((size_t)bh * N_ + kt * 128) * DH_;
    const __nv_bfloat16* klb = Kl + ((size_t)bh * N_ + kt * 128) * DH_;

    #pragma unroll
    for (int i = 0; i < 4; i++) {
        int u  = tid + i * 256;
        int r  = u >> 3, c8 = u & 7;
        uint32_t so = (uint32_t)(r * SC_LDS + c8 * 8) * 2;
        size_t g = (size_t)r * DH_ + c8 * 8;
        CP16(s_ah + so, qhb + g);
        CP16(s_al + so, qlb + g);
        CP16(s_bh + so, khb + g);
        CP16(s_bl + so, klb + g);
    }
    CP_COMMIT();
    CP_WAIT0();
    __syncthreads();

    const uint32_t a_row  = (uint32_t)(wm * 64 + (lane & 15));
    const uint32_t a_coff = (uint32_t)(((lane >> 4) << 3) * 2);
    const uint32_t b_row  = (uint32_t)(wn * 32 + (lane & 7) + ((lane & 16) >> 1));
    const uint32_t b_coff = (uint32_t)((lane & 8) * 2);

    float acc[4][4][4] = {};
    #pragma unroll
    for (int kk = 0; kk < 4; kk++) {
        const uint32_t kb = (uint32_t)(kk * 16 * 2);
        uint32_t bhf[2][4], blf[2][4];
        #pragma unroll
        for (int g = 0; g < 2; g++) {
            uint32_t ba = (b_row + g * 16) * (SC_LDS * 2) + kb + b_coff;
            LDM4(bhf[g], s_bh + ba);
            LDM4(blf[g], s_bl + ba);
        }
        #pragma unroll
        for (int mp = 0; mp < 2; mp++) {
            uint32_t ahf[2][4], alf[2][4];
            #pragma unroll
            for (int i = 0; i < 2; i++) {
                uint32_t aa = (a_row + (mp * 2 + i) * 16) * (SC_LDS * 2) + kb + a_coff;
                LDM4(ahf[i], s_ah + aa);
                LDM4(alf[i], s_al + aa);
            }
            #pragma unroll
            for (int i = 0; i < 2; i++)
                #pragma unroll
                for (int nt = 0; nt < 4; nt++)
                    MMA_BF16(acc[mp*2+i][nt], ahf[i], bhf[nt>>1][(nt&1)*2], bhf[nt>>1][(nt&1)*2+1]);
            #pragma unroll
            for (int i = 0; i < 2; i++)
                #pragma unroll
                for (int nt = 0; nt < 4; nt++)
                    MMA_BF16(acc[mp*2+i][nt], ahf[i], blf[nt>>1][(nt&1)*2], blf[nt>>1][(nt&1)*2+1]);
            #pragma unroll
            for (int i = 0; i < 2; i++)
                #pragma unroll
                for (int nt = 0; nt < 4; nt++)
                    MMA_BF16(acc[mp*2+i][nt], alf[i], bhf[nt>>1][(nt&1)*2], bhf[nt>>1][(nt&1)*2+1]);
        }
    }

    __nv_bfloat16* ph_b = pbh + (size_t)bh * N_ * N_;
    __nv_bfloat16* pl_b = pbl + (size_t)bh * N_ * N_;
    const int rbase_l = wm * 64 + (lane >> 2);
    const int cbase   = wn * 32 + (lane & 3) * 2;
    const bool diag = (kt == qt);

    #pragma unroll
    for (int mt = 0; mt < 4; mt++) {
        #pragma unroll
        for (int rh = 0; rh < 2; rh++) {
            const int row_l = rbase_l + mt * 16 + rh * 8;
            const int row_g = qt * 128 + row_l;
            __nv_bfloat16* phrow = ph_b + (size_t)row_g * N_;
            __nv_bfloat16* plrow = pl_b + (size_t)row_g * N_;
            float s = 0.f;
            #pragma unroll
            for (int nt = 0; nt < 4; nt++) {
                int c = kt * 128 + cbase + nt * 8;
                float e0 = exp_fast(acc[mt][nt][rh * 2 + 0] * 0.125f);
                float e1 = exp_fast(acc[mt][nt][rh * 2 + 1] * 0.125f);
                if (diag) {
                    if (c > row_g)     e0 = 0.f;
                    if (c + 1 > row_g) e1 = 0.f;
                }
                s += e0 + e1;
                __nv_bfloat16 h0, l0, h1, l1;
                bf_split(e0, h0, l0);
                bf_split(e1, h1, l1);
                *(uint32_t*)(phrow + c) = bf_pack(h0, h1);
                *(uint32_t*)(plrow + c) = bf_pack(l0, l1);
            }
            s += __shfl_xor_sync(~0u, s, 1);
            s += __shfl_xor_sync(~0u, s, 2);
            if ((lane & 3) == 0)
                psum_s[wn * 128 + row_l] = s;
        }
    }
    __syncthreads();
    if (tid < 128) {
        float s = psum_s[tid] + psum_s[128 + tid] + psum_s[256 + tid] + psum_s[384 + tid];
        psum[(((size_t)bh * N_) + qt * 128 + tid) * 16 + kt] = s;
    }
}

// ---------------------------------------------------------------------------
// finalize_inv (unchanged)
// ---------------------------------------------------------------------------
__global__ __launch_bounds__(256) void finalize_inv(
    const float* __restrict__ psum, float* __restrict__ ginv)
{
    int r = blockIdx.x * 256 + threadIdx.x;
    int row = r & (N_ - 1);
    int ktmax = row >> 7;
    const float* p = psum + (size_t)r * 16;
    float s = 0.f;
    for (int kt = 0; kt <= ktmax; kt++) s += p[kt];
    ginv[r] = 1.0f / s;
}

// ---------------------------------------------------------------------------
// attn_write (unchanged from R10)
// ---------------------------------------------------------------------------
__global__ __launch_bounds__(256) void attn_write(
    const __nv_bfloat16* __restrict__ pbh, const __nv_bfloat16* __restrict__ pbl,
    const float* __restrict__ ginv, float* __restrict__ attn)
{
    const size_t r = blockIdx.x;
    const int row = blockIdx.x & (N_ - 1);
    const int kmax = ((row >> 7) + 1) << 7;
    const float iv = ginv[r];
    const __nv_bfloat16* phrow = pbh + r * N_;
    const __nv_bfloat16* plrow = pbl + r * N_;
    float* arow = attn + r * N_;
    const int tid = threadIdx.x;

    for (int c = tid * 4; c < kmax; c += 1024) {
        uint2 uh = *(const uint2*)(phrow + c);
        uint2 ul = *(const uint2*)(plrow + c);
        __nv_bfloat162 h01 = *reinterpret_cast<__nv_bfloat162*>(&uh.x);
        __nv_bfloat162 h23 = *reinterpret_cast<__nv_bfloat162*>(&uh.y);
        __nv_bfloat162 l01 = *reinterpret_cast<__nv_bfloat162*>(&ul.x);
        __nv_bfloat162 l23 = *reinterpret_cast<__nv_bfloat162*>(&ul.y);
        float4 o;
        o.x = (__bfloat162float(h01.x) + __bfloat162float(l01.x)) * iv;
        o.y = (__bfloat162float(h01.y) + __bfloat162float(l01.y)) * iv;
        o.z = (__bfloat162float(h23.x) + __bfloat162float(l23.x)) * iv;
        o.w = (__bfloat162float(h23.y) + __bfloat162float(l23.y)) * iv;
        *(float4*)(arow + c) = o;
    }
    const float4 z4 = make_float4(0.f, 0.f, 0.f, 0.f);
    for (int c = kmax + tid * 4; c < N_; c += 1024)
        *(float4*)(arow + c) = z4;
}

// ---------------------------------------------------------------------------
// sa_pipe (reverted to R13-best: 2-stage, chunk 64, SP_LDS 72)
// ---------------------------------------------------------------------------
#define SP_LDS 72
#define SP_PH 0
#define SP_PL 18432
#define SP_VH 36864
#define SP_VL 46080
#define SP_STAGE 55296
#define SP_SMEM (2 * SP_STAGE)

__global__ __launch_bounds__(256) void sa_pipe(
    const __nv_bfloat16* __restrict__ Ph, const __nv_bfloat16* __restrict__ Pl,
    const __nv_bfloat16* __restrict__ Vth, const __nv_bfloat16* __restrict__ Vtl,
    const float* __restrict__ ginv,
    __nv_bfloat16* __restrict__ sahi, __nv_bfloat16* __restrict__ salo)
{
    extern __shared__ __nv_bfloat16 smem[];
    const uint32_t sb0 = smem_u32(smem);
    const int bh = blockIdx.x;
    const int qt = (N_ / 128 - 1) - blockIdx.y;
    const int tid  = threadIdx.x;
    const int lane = tid & 31;
    const int wid  = tid >> 5;
    const int wm   = wid >> 2;
    const int wn   = wid & 3;

    const __nv_bfloat16* phb = Ph + ((size_t)bh * N_ + qt * 128) * N_;
    const __nv_bfloat16* plb = Pl + ((size_t)bh * N_ + qt * 128) * N_;
    const __nv_bfloat16* vhb = Vth + (size_t)bh * DH_ * N_;
    const __nv_bfloat16* vlb = Vtl + (size_t)bh * DH_ * N_;

    float acc[4][2][4] = {};

    const uint32_t a_row  = (uint32_t)(wm * 64 + (lane & 15));
    const uint32_t a_coff = (uint32_t)(((lane >> 4) << 3) * 2);
    const uint32_t b_row  = (uint32_t)(wn * 16 + (lane & 7) + ((lane & 16) >> 1));
    const uint32_t b_coff = (uint32_t)((lane & 8) * 2);

    const int lr = tid >> 3, lc = tid & 7;

    auto load_chunk = [&](int kc, int st) {
        const uint32_t sbs = sb0 + st * SP_STAGE;
        const int kofs = kc * 64 + lc * 8;
        #pragma unroll
        for (int i = 0; i < 4; i++) {
            int r = lr + i * 32;
            uint32_t so = (uint32_t)(r * SP_LDS + lc * 8) * 2;
            size_t g = (size_t)r * N_ + kofs;
            CP16(sbs + SP_PH + so, phb + g);
            CP16(sbs + SP_PL + so, plb + g);
        }
        #pragma unroll
        for (int i = 0; i < 2; i++) {
            int r = lr + i * 32;
            uint32_t so = (uint32_t)(r * SP_LDS + lc * 8) * 2;
            size_t g = (size_t)r * N_ + kofs;
            CP16(sbs + SP_VH + so, vhb + g);
            CP16(sbs + SP_VL + so, vlb + g);
        }
    };

    const int nchunks = (qt + 1) * 2;
    load_chunk(0, 0);
    CP_COMMIT();

    for (int kc = 0; kc < nchunks; kc++) {
        const int cur = kc & 1;
        CP_WAIT0();
        __syncthreads();
        if (kc + 1 < nchunks) {
            load_chunk(kc + 1, cur ^ 1);
            CP_COMMIT();
        }

        const uint32_t sbs = sb0 + cur * SP_STAGE;
        const uint32_t s_ph = sbs + SP_PH, s_pl = sbs + SP_PL;
        const uint32_t s_vh = sbs + SP_VH, s_vl = sbs + SP_VL;

        #pragma unroll
        for (int kk = 0; kk < 4; kk++) {
            const uint32_t kb = (uint32_t)(kk * 16 * 2);
            uint32_t bhf[4], blf[4];
            uint32_t ba = b_row * (SP_LDS * 2) + kb + b_coff;
            LDM4(bhf, s_vh + ba);
            LDM4(blf, s_vl + ba);
            uint32_t ahf[4][4], alf[4][4];
            #pragma unroll
            for (int mt = 0; mt < 4; mt++) {
                uint32_t aa = (a_row + mt * 16) * (SP_LDS * 2) + kb + a_coff;
                LDM4(ahf[mt], s_ph + aa);
                LDM4(alf[mt], s_pl + aa);
            }
            #pragma unroll
            for (int mt = 0; mt < 4; mt++)
                #pragma unroll
                for (int nt = 0; nt < 2; nt++)
                    MMA_BF16(acc[mt][nt], ahf[mt], bhf[nt*2], bhf[nt*2+1]);
            #pragma unroll
            for (int mt = 0; mt < 4; mt++)
                #pragma unroll
                for (int nt = 0; nt < 2; nt++)
                    MMA_BF16(acc[mt][nt], ahf[mt], blf[nt*2], blf[nt*2+1]);
            #pragma unroll
            for (int mt = 0; mt < 4; mt++)
                #pragma unroll
                for (int nt = 0; nt < 2; nt++)
                    MMA_BF16(acc[mt][nt], alf[mt], bhf[nt*2], bhf[nt*2+1]);
        }
    }

    const int b = bh >> 4, h = bh & 15;
    const int row0 = wm * 64 + (lane >> 2);
    const int col0 = wn * 16 + (lane & 3) * 2;
    const float* inv_b = ginv + (size_t)bh * N_;

    float ivr[8];
    #pragma unroll
    for (int mt = 0; mt < 4; mt++)
        #pragma unroll
        for (int rh = 0; rh < 2; rh++)
            ivr[mt * 2 + rh] = inv_b[qt * 128 + row0 + mt * 16 + rh * 8];

    #pragma unroll
    for (int mt = 0; mt < 4; mt++) {
        #pragma unroll
        for (int nt = 0; nt < 2; nt++) {
            #pragma unroll
            for (int r = 0; r < 4; r++) {
                int n  = qt * 128 + row0 + mt * 16 + (r >> 1) * 8;
                int dh = col0 + nt * 8 + (r & 1);
                size_t o = ((size_t)b * N_ + n) * D_ + h * DH_ + dh;
                __nv_bfloat16 vh, vl;
                bf_split(acc[mt][nt][r] * ivr[mt * 2 + (r >> 1)], vh, vl);
                sahi[o] = vh; salo[o] = vl;
            }
        }
    }
}

// ---------------------------------------------------------------------------
extern "C" void kernel_launch(void* const* d_in, const int* in_sizes, int n_in,
                              void* d_out, int out_size)
{
    const float* x     = (const float*)d_in[0];
    const float* Wqkv  = (const float*)d_in[1];
    const float* bqkv  = (const float*)d_in[2];
    const float* Wproj = (const float*)d_in[3];
    const float* bproj = (const float*)d_in[4];
    float* out = (float*)d_out;

    const size_t OUT_ELEMS  = (size_t)B_ * N_ * D_;
    const size_t ATTN_ELEMS = (size_t)B_ * H_ * N_ * N_;

    float* attnp;
    cudaGetSymbolAddress((void**)&attnp, g_attn);
    if ((size_t)out_size >= OUT_ELEMS + ATTN_ELEMS)
        attnp = out + OUT_ELEMS;

    float *ginv, *psum;
    cudaGetSymbolAddress((void**)&ginv, g_inv);
    cudaGetSymbolAddress((void**)&psum, g_psum);

    __nv_bfloat16 *xhi, *xlo, *wqhi, *wqlo, *wphi, *wplo, *sahi, *salo;
    __nv_bfloat16 *qh, *ql, *kh, *kl, *vth, *vtl, *pbh, *pbl;
    cudaGetSymbolAddress((void**)&xhi,  g_xhi);
    cudaGetSymbolAddress((void**)&xlo,  g_xlo);
    cudaGetSymbolAddress((void**)&wqhi, g_wqhi);
    cudaGetSymbolAddress((void**)&wqlo, g_wqlo);
    cudaGetSymbolAddress((void**)&wphi, g_wphi);
    cudaGetSymbolAddress((void**)&wplo, g_wplo);
    cudaGetSymbolAddress((void**)&sahi, g_sahi);
    cudaGetSymbolAddress((void**)&salo, g_salo);
    cudaGetSymbolAddress((void**)&qh,   g_qh);
    cudaGetSymbolAddress((void**)&ql,   g_ql);
    cudaGetSymbolAddress((void**)&kh,   g_kh);
    cudaGetSymbolAddress((void**)&kl,   g_kl);
    cudaGetSymbolAddress((void**)&vth,  g_vth);
    cudaGetSymbolAddress((void**)&vtl,  g_vtl);
    cudaGetSymbolAddress((void**)&pbh,  g_pbh);
    cudaGetSymbolAddress((void**)&pbl,  g_pbl);

    cudaFuncSetAttribute(gemm_pipe<0>, cudaFuncAttributeMaxDynamicSharedMemorySize, GP_SMEM);
    cudaFuncSetAttribute(gemm_pipe<1>, cudaFuncAttributeMaxDynamicSharedMemorySize, GP_SMEM);
    cudaFuncSetAttribute(scores_exp,   cudaFuncAttributeMaxDynamicSharedMemorySize, SC_SMEM);
    cudaFuncSetAttribute(sa_pipe,      cudaFuncAttributeMaxDynamicSharedMemorySize, SP_SMEM);

    // One-time stream/event creation (pre-capture on the correctness call;
    // never destroyed, so capture never sees create/destroy of these objects).
    static cudaStream_t s2 = nullptr;
    static cudaEvent_t evFork = nullptr, evJoin = nullptr;
    static bool stream_ok = false;
    if (!s2) {
        stream_ok = (cudaStreamCreateWithFlags(&s2, cudaStreamNonBlocking) == cudaSuccess)
                 && (cudaEventCreateWithFlags(&evFork, cudaEventDisableTiming) == cudaSuccess)
                 && (cudaEventCreateWithFlags(&evJoin, cudaEventDisableTiming) == cudaSuccess);
    }

    split_all<<<XBLK + WQBLK + WPBLK, 256>>>(
        x, Wqkv, Wproj, xhi, xlo, wqhi, wqlo, wphi, wplo);

    gemm_pipe<0><<<dim3(M_ / 128, J3_ / 128), 256, GP_SMEM>>>(
        xhi, xlo, wqhi, wqlo, bqkv, nullptr, kh, kl, qh, ql, vth, vtl);

    scores_exp<<<dim3(N_ / 128, N_ / 128, B_ * H_), 256, SC_SMEM>>>(
        qh, ql, kh, kl, pbh, pbl, psum);

    finalize_inv<<<(B_ * H_ * N_) / 256, 256>>>(psum, ginv);

    if (stream_ok) {
        // Fork: sa_pipe (tensor-bound) runs on s2 concurrent with
        // attn_write (DRAM-bound) on the main stream.
        cudaEventRecord(evFork, 0);
        cudaStreamWaitEvent(s2, evFork, 0);

        sa_pipe<<<dim3(B_ * H_, N_ / 128), 256, SP_SMEM, s2>>>(
            pbh, pbl, vth, vtl, ginv, sahi, salo);

        attn_write<<<B_ * H_ * N_, 256>>>(pbh, pbl, ginv, attnp);

        cudaEventRecord(evJoin, s2);
        cudaStreamWaitEvent(0, evJoin, 0);
    } else {
        attn_write<<<B_ * H_ * N_, 256>>>(pbh, pbl, ginv, attnp);
        sa_pipe<<<dim3(B_ * H_, N_ / 128), 256, SP_SMEM>>>(
            pbh, pbl, vth, vtl, ginv, sahi, salo);
    }

    gemm_pipe<1><<<dim3(M_ / 128, D_ / 128), 256, GP_SMEM>>>(
        sahi, salo, wphi, wplo, bproj, out,
        nullptr, nullptr, nullptr, nullptr, nullptr, nullptr);
}

// round 16
// speedup vs baseline: 1.0268x; 1.0042x over previous
#include <cuda_runtime.h>
#include <cuda_bf16.h>
#include <math.h>
#include <stdint.h>

// Problem constants
#define B_  2
#define N_  2048
#define D_  1024
#define H_  16
#define DH_ 64
#define E3_ 192
#define J3_ 3072
#define M_  4096

// ---------------------------------------------------------------------------
// Scratch (device globals)
// ---------------------------------------------------------------------------
__device__ float g_attn[(size_t)B_*H_*N_*N_];
__device__ float g_inv [(size_t)B_*H_*N_];
__device__ float g_psum[(size_t)B_*H_*N_*16];

__device__ __nv_bfloat16 g_xhi [(size_t)M_*D_];
__device__ __nv_bfloat16 g_xlo [(size_t)M_*D_];
__device__ __nv_bfloat16 g_wqhi[(size_t)J3_*D_];
__device__ __nv_bfloat16 g_wqlo[(size_t)J3_*D_];
__device__ __nv_bfloat16 g_wphi[(size_t)D_*D_];
__device__ __nv_bfloat16 g_wplo[(size_t)D_*D_];
__device__ __nv_bfloat16 g_sahi[(size_t)M_*D_];
__device__ __nv_bfloat16 g_salo[(size_t)M_*D_];

__device__ __nv_bfloat16 g_qh[(size_t)B_*H_*N_*DH_];
__device__ __nv_bfloat16 g_ql[(size_t)B_*H_*N_*DH_];
__device__ __nv_bfloat16 g_kh[(size_t)B_*H_*N_*DH_];
__device__ __nv_bfloat16 g_kl[(size_t)B_*H_*N_*DH_];
__device__ __nv_bfloat16 g_vth[(size_t)B_*H_*DH_*N_];
__device__ __nv_bfloat16 g_vtl[(size_t)B_*H_*DH_*N_];

__device__ __nv_bfloat16 g_pbh[(size_t)B_*H_*N_*N_];
__device__ __nv_bfloat16 g_pbl[(size_t)B_*H_*N_*N_];

// ---------------------------------------------------------------------------
// Helpers
// ---------------------------------------------------------------------------
__device__ __forceinline__ uint32_t smem_u32(const void* p) {
    uint32_t a;
    asm("{ .reg .u64 t; cvta.to.shared.u64 t, %1; cvt.u32.u64 %0, t; }"
        : "=r"(a) : "l"(p));
    return a;
}

#define LDM4(r, addr)                                                         \
    asm volatile("ldmatrix.sync.aligned.m8n8.x4.shared.b16 {%0,%1,%2,%3}, [%4];" \
        : "=r"((r)[0]), "=r"((r)[1]), "=r"((r)[2]), "=r"((r)[3])              \
        : "r"(addr))

#define MMA_BF16(c, a, b0, b1)                                                \
    asm volatile("mma.sync.aligned.m16n8k16.row.col.f32.bf16.bf16.f32 "       \
        "{%0,%1,%2,%3}, {%4,%5,%6,%7}, {%8,%9}, {%0,%1,%2,%3};"               \
        : "+f"((c)[0]), "+f"((c)[1]), "+f"((c)[2]), "+f"((c)[3])              \
        : "r"((a)[0]), "r"((a)[1]), "r"((a)[2]), "r"((a)[3]), "r"(b0), "r"(b1))

#define CP16(dst, src)                                                        \
    asm volatile("cp.async.cg.shared.global [%0], [%1], 16;"                  \
        :: "r"(dst), "l"(src))
#define CP_COMMIT() asm volatile("cp.async.commit_group;" ::: "memory")
#define CP_WAIT0()  asm volatile("cp.async.wait_group 0;" ::: "memory")
#define CP_WAIT1()  asm volatile("cp.async.wait_group 1;" ::: "memory")

__device__ __forceinline__ void bf_split(float v, __nv_bfloat16& h, __nv_bfloat16& l) {
    h = __float2bfloat16(v);
    l = __float2bfloat16(v - __bfloat162float(h));
}

__device__ __forceinline__ uint32_t bf_pack(__nv_bfloat16 a, __nv_bfloat16 b) {
    __nv_bfloat162 t(a, b);
    return *reinterpret_cast<uint32_t*>(&t);
}

// Fast exp on FMA pipes (validated R8-R15)
__device__ __forceinline__ float exp_fast(float x) {
    float y = x * 1.4426950408889634f;
    float nf = rintf(y);
    int   ni = (int)nf;
    float f = y - nf;
    float p = 1.5403530393e-4f;
    p = fmaf(p, f, 1.3333558146e-3f);
    p = fmaf(p, f, 9.6181291076e-3f);
    p = fmaf(p, f, 5.5504108664e-2f);
    p = fmaf(p, f, 2.4022650696e-1f);
    p = fmaf(p, f, 6.9314718246e-1f);
    p = fmaf(p, f, 1.0f);
    return p * __int_as_float((ni + 127) << 23);
}

// 64 B-row XOR-unit swizzle (validated R13)
#define GP_OFF(r, u) ((uint32_t)((r) * 64 + (((u) ^ (((r) >> 1) & 3)) << 4)))

// ---------------------------------------------------------------------------
// Fused split kernel (unchanged)
// ---------------------------------------------------------------------------
#define XBLK (M_ * D_ / 256)
#define WQBLK (J3_ * D_ / 256)
#define WPBLK (D_ * D_ / 256)

__global__ __launch_bounds__(256) void split_all(
    const float* __restrict__ x, const float* __restrict__ Wqkv,
    const float* __restrict__ Wproj,
    __nv_bfloat16* __restrict__ xhi, __nv_bfloat16* __restrict__ xlo,
    __nv_bfloat16* __restrict__ wqhi, __nv_bfloat16* __restrict__ wqlo,
    __nv_bfloat16* __restrict__ wphi, __nv_bfloat16* __restrict__ wplo)
{
    int blk = blockIdx.x;
    if (blk < XBLK) {
        int i = blk * 256 + threadIdx.x;
        float v = x[i];
        __nv_bfloat16 h, l; bf_split(v, h, l);
        xhi[i] = h; xlo[i] = l;
    } else if (blk < XBLK + WQBLK) {
        int idx = (blk - XBLK) * 256 + threadIdx.x;
        int j = idx >> 10, d = idx & 1023;
        int h = j / E3_, e = j % E3_;
        float v = Wqkv[((size_t)h * D_ + d) * E3_ + e];
        __nv_bfloat16 vh, vl; bf_split(v, vh, vl);
        wqhi[idx] = vh; wqlo[idx] = vl;
    } else {
        int i = (blk - XBLK - WQBLK) * 256 + threadIdx.x;
        float v = Wproj[i];
        __nv_bfloat16 h, l; bf_split(v, h, l);
        wphi[i] = h; wplo[i] = l;
    }
}

// ---------------------------------------------------------------------------
// gemm_pipe (unchanged from R13 — validated 3-stage)
// ---------------------------------------------------------------------------
#define GP_AH 0
#define GP_AL 8192
#define GP_BH 16384
#define GP_BL 24576
#define GP_STAGE 32768
#define GP_SMEM (3 * GP_STAGE)

template<int MODE>
__global__ __launch_bounds__(256) void gemm_pipe(
    const __nv_bfloat16* __restrict__ Ahi, const __nv_bfloat16* __restrict__ Alo,
    const __nv_bfloat16* __restrict__ Bhi, const __nv_bfloat16* __restrict__ Blo,
    const float* __restrict__ bias,
    float* __restrict__ oF,
    __nv_bfloat16* __restrict__ okh, __nv_bfloat16* __restrict__ okl,
    __nv_bfloat16* __restrict__ oqh, __nv_bfloat16* __restrict__ oql,
    __nv_bfloat16* __restrict__ ovh, __nv_bfloat16* __restrict__ ovl)
{
    extern __shared__ __nv_bfloat16 smem[];
    const uint32_t sb0 = smem_u32(smem);
    const int tid  = threadIdx.x;
    const int lane = tid & 31;
    const int wid  = tid >> 5;
    const int wm   = wid >> 2;
    const int wn   = wid & 3;
    const int m0 = blockIdx.x * 128;
    const int n0 = blockIdx.y * 128;

    float acc[4][4][4] = {};

    const int a_row  = wm * 64 + (lane & 15);
    const int a_half = lane >> 4;
    const int b_row  = wn * 32 + (lane & 7) + ((lane & 16) >> 1);
    const int b_half = (lane & 8) >> 3;

    const int lr0 = tid >> 2, lc0 = tid & 3;
    const int lr1 = lr0 + 64;

    auto load_chunk = [&](int kc, int st) {
        const uint32_t sbs = sb0 + st * GP_STAGE;
        const uint32_t so0 = GP_OFF(lr0, lc0);
        const uint32_t so1 = GP_OFF(lr1, lc0);
        size_t ga0 = (size_t)(m0 + lr0) * D_ + kc * 32 + lc0 * 8;
        size_t ga1 = (size_t)(m0 + lr1) * D_ + kc * 32 + lc0 * 8;
        size_t gb0 = (size_t)(n0 + lr0) * D_ + kc * 32 + lc0 * 8;
        size_t gb1 = (size_t)(n0 + lr1) * D_ + kc * 32 + lc0 * 8;
        CP16(sbs + GP_AH + so0, Ahi + ga0);
        CP16(sbs + GP_AH + so1, Ahi + ga1);
        CP16(sbs + GP_AL + so0, Alo + ga0);
        CP16(sbs + GP_AL + so1, Alo + ga1);
        CP16(sbs + GP_BH + so0, Bhi + gb0);
        CP16(sbs + GP_BH + so1, Bhi + gb1);
        CP16(sbs + GP_BL + so0, Blo + gb0);
        CP16(sbs + GP_BL + so1, Blo + gb1);
    };

    load_chunk(0, 0);
    CP_COMMIT();
    load_chunk(1, 1);
    CP_COMMIT();

    int st_cur = 0, st_next = 2;
    for (int kc = 0; kc < 32; kc++) {
        if (kc + 2 < 32) CP_WAIT1();
        else             CP_WAIT0();
        __syncthreads();
        if (kc + 2 < 32) {
            load_chunk(kc + 2, st_next);
            CP_COMMIT();
        }

        const uint32_t sbs = sb0 + st_cur * GP_STAGE;
        const uint32_t s_ah = sbs + GP_AH, s_al = sbs + GP_AL;
        const uint32_t s_bh = sbs + GP_BH, s_bl = sbs + GP_BL;

        #pragma unroll
        for (int kk = 0; kk < 2; kk++) {
            uint32_t bhf[2][4], blf[2][4];
            #pragma unroll
            for (int g = 0; g < 2; g++) {
                int br = b_row + g * 16;
                uint32_t ba = GP_OFF(br, kk * 2 + b_half);
                LDM4(bhf[g], s_bh + ba);
                LDM4(blf[g], s_bl + ba);
            }
            #pragma unroll
            for (int mp = 0; mp < 2; mp++) {
                uint32_t ahf[2][4], alf[2][4];
                #pragma unroll
                for (int i = 0; i < 2; i++) {
                    int ar = a_row + (mp * 2 + i) * 16;
                    uint32_t aa = GP_OFF(ar, kk * 2 + a_half);
                    LDM4(ahf[i], s_ah + aa);
                    LDM4(alf[i], s_al + aa);
                }
                #pragma unroll
                for (int i = 0; i < 2; i++)
                    #pragma unroll
                    for (int nt = 0; nt < 4; nt++)
                        MMA_BF16(acc[mp*2+i][nt], ahf[i], bhf[nt>>1][(nt&1)*2], bhf[nt>>1][(nt&1)*2+1]);
                #pragma unroll
                for (int i = 0; i < 2; i++)
                    #pragma unroll
                    for (int nt = 0; nt < 4; nt++)
                        MMA_BF16(acc[mp*2+i][nt], ahf[i], blf[nt>>1][(nt&1)*2], blf[nt>>1][(nt&1)*2+1]);
                #pragma unroll
                for (int i = 0; i < 2; i++)
                    #pragma unroll
                    for (int nt = 0; nt < 4; nt++)
                        MMA_BF16(acc[mp*2+i][nt], alf[i], bhf[nt>>1][(nt&1)*2], bhf[nt>>1][(nt&1)*2+1]);
            }
        }

        st_cur  = (st_cur  == 2) ? 0 : st_cur + 1;
        st_next = (st_next == 2) ? 0 : st_next + 1;
    }

    const int row0 = wm * 64 + (lane >> 2);
    const int col0 = wn * 32 + (lane & 3) * 2;
    #pragma unroll
    for (int mt = 0; mt < 4; mt++) {
        #pragma unroll
        for (int nt = 0; nt < 4; nt++) {
            #pragma unroll
            for (int r = 0; r < 4; r++) {
                int m = m0 + row0 + mt * 16 + (r >> 1) * 8;
                int j = n0 + col0 + nt * 8 + (r & 1);
                float val = acc[mt][nt][r] + bias[j];
                if (MODE == 1) {
                    oF[(size_t)m * D_ + j] = val;
                } else {
                    int b = m >> 11, n = m & (N_ - 1);
                    int h = j / E3_, e = j % E3_;
                    __nv_bfloat16 vh, vl; bf_split(val, vh, vl);
                    if (e < DH_) {
                        size_t o = ((size_t)(b * H_ + h) * N_ + n) * DH_ + e;
                        okh[o] = vh; okl[o] = vl;
                    } else if (e < 2 * DH_) {
                        size_t o = ((size_t)(b * H_ + h) * N_ + n) * DH_ + (e - DH_);
                        oqh[o] = vh; oql[o] = vl;
                    } else {
                        size_t o = ((size_t)(b * H_ + h) * DH_ + (e - 2 * DH_)) * N_ + n;
                        ovh[o] = vh; ovl[o] = vl;
                    }
                }
            }
        }
    }
}

// ---------------------------------------------------------------------------
// scores_exp (unchanged from R10/R13)
// ---------------------------------------------------------------------------
#define SC_LDS 72
#define SC_TILE (128 * SC_LDS)
#define SC_AH 0
#define SC_AL (1 * SC_TILE)
#define SC_BH (2 * SC_TILE)
#define SC_BL (3 * SC_TILE)
#define SC_PS_OFF (4 * SC_TILE * 2)
#define SC_SMEM (4 * SC_TILE * 2 + 2048)

__global__ __launch_bounds__(256) void scores_exp(
    const __nv_bfloat16* __restrict__ Qh, const __nv_bfloat16* __restrict__ Ql,
    const __nv_bfloat16* __restrict__ Kh, const __nv_bfloat16* __restrict__ Kl,
    __nv_bfloat16* __restrict__ pbh, __nv_bfloat16* __restrict__ pbl,
    float* __restrict__ psum)
{
    const int qt = blockIdx.x, kt = blockIdx.y, bh = blockIdx.z;
    if (kt > qt) return;

    extern __shared__ __nv_bfloat16 smem[];
    const uint32_t sb0 = smem_u32(smem);
    float* psum_s = (float*)((char*)smem + SC_PS_OFF);
    const int tid  = threadIdx.x;
    const int lane = tid & 31;
    const int wid  = tid >> 5;
    const int wm   = wid >> 2;
    const int wn   = wid & 3;

    const uint32_t s_ah = sb0 + SC_AH * 2;
    const uint32_t s_al = sb0 + SC_AL * 2;
    const uint32_t s_bh = sb0 + SC_BH * 2;
    const uint32_t s_bl = sb0 + SC_BL * 2;

    const __nv_bfloat16* qhb = Qh + ((size_t)bh * N_ + qt * 128) * DH_;
    const __nv_bfloat16* qlb = Ql + ((size_t)bh * N_ + qt * 128) * DH_;
    const __nv_bfloat16* khb = Kh + ((size_t)bh * N_ + kt * 128) * DH_;
    const __nv_bfloat16* klb = Kl + ((size_t)bh * N_ + kt * 128) * DH_;

    #pragma unroll
    for (int i = 0; i < 4; i++) {
        int u  = tid + i * 256;
        int r  = u >> 3, c8 = u & 7;
        uint32_t so = (uint32_t)(r * SC_LDS + c8 * 8) * 2;
        size_t g = (size_t)r * DH_ + c8 * 8;
        CP16(s_ah + so, qhb + g);
        CP16(s_al + so, qlb + g);
        CP16(s_bh + so, khb + g);
        CP16(s_bl + so, klb + g);
    }
    CP_COMMIT();
    CP_WAIT0();
    __syncthreads();

    const uint32_t a_row  = (uint32_t)(wm * 64 + (lane & 15));
    const uint32_t a_coff = (uint32_t)(((lane >> 4) << 3) * 2);
    const uint32_t b_row  = (uint32_t)(wn * 32 + (lane & 7) + ((lane & 16) >> 1));
    const uint32_t b_coff = (uint32_t)((lane & 8) * 2);

    float acc[4][4][4] = {};
    #pragma unroll
    for (int kk = 0; kk < 4; kk++) {
        const uint32_t kb = (uint32_t)(kk * 16 * 2);
        uint32_t bhf[2][4], blf[2][4];
        #pragma unroll
        for (int g = 0; g < 2; g++) {
            uint32_t ba = (b_row + g * 16) * (SC_LDS * 2) + kb + b_coff;
            LDM4(bhf[g], s_bh + ba);
            LDM4(blf[g], s_bl + ba);
        }
        #pragma unroll
        for (int mp = 0; mp < 2; mp++) {
            uint32_t ahf[2][4], alf[2][4];
            #pragma unroll
            for (int i = 0; i < 2; i++) {
                uint32_t aa = (a_row + (mp * 2 + i) * 16) * (SC_LDS * 2) + kb + a_coff;
                LDM4(ahf[i], s_ah + aa);
                LDM4(alf[i], s_al + aa);
            }
            #pragma unroll
            for (int i = 0; i < 2; i++)
                #pragma unroll
                for (int nt = 0; nt < 4; nt++)
                    MMA_BF16(acc[mp*2+i][nt], ahf[i], bhf[nt>>1][(nt&1)*2], bhf[nt>>1][(nt&1)*2+1]);
            #pragma unroll
            for (int i = 0; i < 2; i++)
                #pragma unroll
                for (int nt = 0; nt < 4; nt++)
                    MMA_BF16(acc[mp*2+i][nt], ahf[i], blf[nt>>1][(nt&1)*2], blf[nt>>1][(nt&1)*2+1]);
            #pragma unroll
            for (int i = 0; i < 2; i++)
                #pragma unroll
                for (int nt = 0; nt < 4; nt++)
                    MMA_BF16(acc[mp*2+i][nt], alf[i], bhf[nt>>1][(nt&1)*2], bhf[nt>>1][(nt&1)*2+1]);
        }
    }

    __nv_bfloat16* ph_b = pbh + (size_t)bh * N_ * N_;
    __nv_bfloat16* pl_b = pbl + (size_t)bh * N_ * N_;
    const int rbase_l = wm * 64 + (lane >> 2);
    const int cbase   = wn * 32 + (lane & 3) * 2;
    const bool diag = (kt == qt);

    #pragma unroll
    for (int mt = 0; mt < 4; mt++) {
        #pragma unroll
        for (int rh = 0; rh < 2; rh++) {
            const int row_l = rbase_l + mt * 16 + rh * 8;
            const int row_g = qt * 128 + row_l;
            __nv_bfloat16* phrow = ph_b + (size_t)row_g * N_;
            __nv_bfloat16* plrow = pl_b + (size_t)row_g * N_;
            float s = 0.f;
            #pragma unroll
            for (int nt = 0; nt < 4; nt++) {
                int c = kt * 128 + cbase + nt * 8;
                float e0 = exp_fast(acc[mt][nt][rh * 2 + 0] * 0.125f);
                float e1 = exp_fast(acc[mt][nt][rh * 2 + 1] * 0.125f);
                if (diag) {
                    if (c > row_g)     e0 = 0.f;
                    if (c + 1 > row_g) e1 = 0.f;
                }
                s += e0 + e1;
                __nv_bfloat16 h0, l0, h1, l1;
                bf_split(e0, h0, l0);
                bf_split(e1, h1, l1);
                *(uint32_t*)(phrow + c) = bf_pack(h0, h1);
                *(uint32_t*)(plrow + c) = bf_pack(l0, l1);
            }
            s += __shfl_xor_sync(~0u, s, 1);
            s += __shfl_xor_sync(~0u, s, 2);
            if ((lane & 3) == 0)
                psum_s[wn * 128 + row_l] = s;
        }
    }
    __syncthreads();
    if (tid < 128) {
        float s = psum_s[tid] + psum_s[128 + tid] + psum_s[256 + tid] + psum_s[384 + tid];
        psum[(((size_t)bh * N_) + qt * 128 + tid) * 16 + kt] = s;
    }
}

// ---------------------------------------------------------------------------
// finalize_inv (unchanged)
// ---------------------------------------------------------------------------
__global__ __launch_bounds__(256) void finalize_inv(
    const float* __restrict__ psum, float* __restrict__ ginv)
{
    int r = blockIdx.x * 256 + threadIdx.x;
    int row = r & (N_ - 1);
    int ktmax = row >> 7;
    const float* p = psum + (size_t)r * 16;
    float s = 0.f;
    for (int kt = 0; kt <= ktmax; kt++) s += p[kt];
    ginv[r] = 1.0f / s;
}

// ---------------------------------------------------------------------------
// attn_write (unchanged from R10)
// ---------------------------------------------------------------------------
__global__ __launch_bounds__(256) void attn_write(
    const __nv_bfloat16* __restrict__ pbh, const __nv_bfloat16* __restrict__ pbl,
    const float* __restrict__ ginv, float* __restrict__ attn)
{
    const size_t r = blockIdx.x;
    const int row = blockIdx.x & (N_ - 1);
    const int kmax = ((row >> 7) + 1) << 7;
    const float iv = ginv[r];
    const __nv_bfloat16* phrow = pbh + r * N_;
    const __nv_bfloat16* plrow = pbl + r * N_;
    float* arow = attn + r * N_;
    const int tid = threadIdx.x;

    for (int c = tid * 4; c < kmax; c += 1024) {
        uint2 uh = *(const uint2*)(phrow + c);
        uint2 ul = *(const uint2*)(plrow + c);
        __nv_bfloat162 h01 = *reinterpret_cast<__nv_bfloat162*>(&uh.x);
        __nv_bfloat162 h23 = *reinterpret_cast<__nv_bfloat162*>(&uh.y);
        __nv_bfloat162 l01 = *reinterpret_cast<__nv_bfloat162*>(&ul.x);
        __nv_bfloat162 l23 = *reinterpret_cast<__nv_bfloat162*>(&ul.y);
        float4 o;
        o.x = (__bfloat162float(h01.x) + __bfloat162float(l01.x)) * iv;
        o.y = (__bfloat162float(h01.y) + __bfloat162float(l01.y)) * iv;
        o.z = (__bfloat162float(h23.x) + __bfloat162float(l23.x)) * iv;
        o.w = (__bfloat162float(h23.y) + __bfloat162float(l23.y)) * iv;
        *(float4*)(arow + c) = o;
    }
    const float4 z4 = make_float4(0.f, 0.f, 0.f, 0.f);
    for (int c = kmax + tid * 4; c < N_; c += 1024)
        *(float4*)(arow + c) = z4;
}

// ---------------------------------------------------------------------------
// sa_pipe (R13-best: 2-stage, chunk 64, SP_LDS 72)
// ---------------------------------------------------------------------------
#define SP_LDS 72
#define SP_PH 0
#define SP_PL 18432
#define SP_VH 36864
#define SP_VL 46080
#define SP_STAGE 55296
#define SP_SMEM (2 * SP_STAGE)

__global__ __launch_bounds__(256) void sa_pipe(
    const __nv_bfloat16* __restrict__ Ph, const __nv_bfloat16* __restrict__ Pl,
    const __nv_bfloat16* __restrict__ Vth, const __nv_bfloat16* __restrict__ Vtl,
    const float* __restrict__ ginv,
    __nv_bfloat16* __restrict__ sahi, __nv_bfloat16* __restrict__ salo)
{
    extern __shared__ __nv_bfloat16 smem[];
    const uint32_t sb0 = smem_u32(smem);
    const int bh = blockIdx.x;
    const int qt = (N_ / 128 - 1) - blockIdx.y;
    const int tid  = threadIdx.x;
    const int lane = tid & 31;
    const int wid  = tid >> 5;
    const int wm   = wid >> 2;
    const int wn   = wid & 3;

    const __nv_bfloat16* phb = Ph + ((size_t)bh * N_ + qt * 128) * N_;
    const __nv_bfloat16* plb = Pl + ((size_t)bh * N_ + qt * 128) * N_;
    const __nv_bfloat16* vhb = Vth + (size_t)bh * DH_ * N_;
    const __nv_bfloat16* vlb = Vtl + (size_t)bh * DH_ * N_;

    float acc[4][2][4] = {};

    const uint32_t a_row  = (uint32_t)(wm * 64 + (lane & 15));
    const uint32_t a_coff = (uint32_t)(((lane >> 4) << 3) * 2);
    const uint32_t b_row  = (uint32_t)(wn * 16 + (lane & 7) + ((lane & 16) >> 1));
    const uint32_t b_coff = (uint32_t)((lane & 8) * 2);

    const int lr = tid >> 3, lc = tid & 7;

    auto load_chunk = [&](int kc, int st) {
        const uint32_t sbs = sb0 + st * SP_STAGE;
        const int kofs = kc * 64 + lc * 8;
        #pragma unroll
        for (int i = 0; i < 4; i++) {
            int r = lr + i * 32;
            uint32_t so = (uint32_t)(r * SP_LDS + lc * 8) * 2;
            size_t g = (size_t)r * N_ + kofs;
            CP16(sbs + SP_PH + so, phb + g);
            CP16(sbs + SP_PL + so, plb + g);
        }
        #pragma unroll
        for (int i = 0; i < 2; i++) {
            int r = lr + i * 32;
            uint32_t so = (uint32_t)(r * SP_LDS + lc * 8) * 2;
            size_t g = (size_t)r * N_ + kofs;
            CP16(sbs + SP_VH + so, vhb + g);
            CP16(sbs + SP_VL + so, vlb + g);
        }
    };

    const int nchunks = (qt + 1) * 2;
    load_chunk(0, 0);
    CP_COMMIT();

    for (int kc = 0; kc < nchunks; kc++) {
        const int cur = kc & 1;
        CP_WAIT0();
        __syncthreads();
        if (kc + 1 < nchunks) {
            load_chunk(kc + 1, cur ^ 1);
            CP_COMMIT();
        }

        const uint32_t sbs = sb0 + cur * SP_STAGE;
        const uint32_t s_ph = sbs + SP_PH, s_pl = sbs + SP_PL;
        const uint32_t s_vh = sbs + SP_VH, s_vl = sbs + SP_VL;

        #pragma unroll
        for (int kk = 0; kk < 4; kk++) {
            const uint32_t kb = (uint32_t)(kk * 16 * 2);
            uint32_t bhf[4], blf[4];
            uint32_t ba = b_row * (SP_LDS * 2) + kb + b_coff;
            LDM4(bhf, s_vh + ba);
            LDM4(blf, s_vl + ba);
            uint32_t ahf[4][4], alf[4][4];
            #pragma unroll
            for (int mt = 0; mt < 4; mt++) {
                uint32_t aa = (a_row + mt * 16) * (SP_LDS * 2) + kb + a_coff;
                LDM4(ahf[mt], s_ph + aa);
                LDM4(alf[mt], s_pl + aa);
            }
            #pragma unroll
            for (int mt = 0; mt < 4; mt++)
                #pragma unroll
                for (int nt = 0; nt < 2; nt++)
                    MMA_BF16(acc[mt][nt], ahf[mt], bhf[nt*2], bhf[nt*2+1]);
            #pragma unroll
            for (int mt = 0; mt < 4; mt++)
                #pragma unroll
                for (int nt = 0; nt < 2; nt++)
                    MMA_BF16(acc[mt][nt], ahf[mt], blf[nt*2], blf[nt*2+1]);
            #pragma unroll
            for (int mt = 0; mt < 4; mt++)
                #pragma unroll
                for (int nt = 0; nt < 2; nt++)
                    MMA_BF16(acc[mt][nt], alf[mt], bhf[nt*2], bhf[nt*2+1]);
        }
    }

    const int b = bh >> 4, h = bh & 15;
    const int row0 = wm * 64 + (lane >> 2);
    const int col0 = wn * 16 + (lane & 3) * 2;
    const float* inv_b = ginv + (size_t)bh * N_;

    float ivr[8];
    #pragma unroll
    for (int mt = 0; mt < 4; mt++)
        #pragma unroll
        for (int rh = 0; rh < 2; rh++)
            ivr[mt * 2 + rh] = inv_b[qt * 128 + row0 + mt * 16 + rh * 8];

    #pragma unroll
    for (int mt = 0; mt < 4; mt++) {
        #pragma unroll
        for (int nt = 0; nt < 2; nt++) {
            #pragma unroll
            for (int r = 0; r < 4; r++) {
                int n  = qt * 128 + row0 + mt * 16 + (r >> 1) * 8;
                int dh = col0 + nt * 8 + (r & 1);
                size_t o = ((size_t)b * N_ + n) * D_ + h * DH_ + dh;
                __nv_bfloat16 vh, vl;
                bf_split(acc[mt][nt][r] * ivr[mt * 2 + (r >> 1)], vh, vl);
                sahi[o] = vh; salo[o] = vl;
            }
        }
    }
}

// ---------------------------------------------------------------------------
extern "C" void kernel_launch(void* const* d_in, const int* in_sizes, int n_in,
                              void* d_out, int out_size)
{
    const float* x     = (const float*)d_in[0];
    const float* Wqkv  = (const float*)d_in[1];
    const float* bqkv  = (const float*)d_in[2];
    const float* Wproj = (const float*)d_in[3];
    const float* bproj = (const float*)d_in[4];
    float* out = (float*)d_out;

    const size_t OUT_ELEMS  = (size_t)B_ * N_ * D_;
    const size_t ATTN_ELEMS = (size_t)B_ * H_ * N_ * N_;

    float* attnp;
    cudaGetSymbolAddress((void**)&attnp, g_attn);
    if ((size_t)out_size >= OUT_ELEMS + ATTN_ELEMS)
        attnp = out + OUT_ELEMS;

    float *ginv, *psum;
    cudaGetSymbolAddress((void**)&ginv, g_inv);
    cudaGetSymbolAddress((void**)&psum, g_psum);

    __nv_bfloat16 *xhi, *xlo, *wqhi, *wqlo, *wphi, *wplo, *sahi, *salo;
    __nv_bfloat16 *qh, *ql, *kh, *kl, *vth, *vtl, *pbh, *pbl;
    cudaGetSymbolAddress((void**)&xhi,  g_xhi);
    cudaGetSymbolAddress((void**)&xlo,  g_xlo);
    cudaGetSymbolAddress((void**)&wqhi, g_wqhi);
    cudaGetSymbolAddress((void**)&wqlo, g_wqlo);
    cudaGetSymbolAddress((void**)&wphi, g_wphi);
    cudaGetSymbolAddress((void**)&wplo, g_wplo);
    cudaGetSymbolAddress((void**)&sahi, g_sahi);
    cudaGetSymbolAddress((void**)&salo, g_salo);
    cudaGetSymbolAddress((void**)&qh,   g_qh);
    cudaGetSymbolAddress((void**)&ql,   g_ql);
    cudaGetSymbolAddress((void**)&kh,   g_kh);
    cudaGetSymbolAddress((void**)&kl,   g_kl);
    cudaGetSymbolAddress((void**)&vth,  g_vth);
    cudaGetSymbolAddress((void**)&vtl,  g_vtl);
    cudaGetSymbolAddress((void**)&pbh,  g_pbh);
    cudaGetSymbolAddress((void**)&pbl,  g_pbl);

    cudaFuncSetAttribute(gemm_pipe<0>, cudaFuncAttributeMaxDynamicSharedMemorySize, GP_SMEM);
    cudaFuncSetAttribute(gemm_pipe<1>, cudaFuncAttributeMaxDynamicSharedMemorySize, GP_SMEM);
    cudaFuncSetAttribute(scores_exp,   cudaFuncAttributeMaxDynamicSharedMemorySize, SC_SMEM);
    cudaFuncSetAttribute(sa_pipe,      cudaFuncAttributeMaxDynamicSharedMemorySize, SP_SMEM);

    // One-time stream/event creation (pre-capture; never destroyed).
    static cudaStream_t s2 = nullptr;
    static cudaEvent_t evFork = nullptr, evJoin = nullptr;
    static bool stream_ok = false;
    if (!s2) {
        stream_ok = (cudaStreamCreateWithFlags(&s2, cudaStreamNonBlocking) == cudaSuccess)
                 && (cudaEventCreateWithFlags(&evFork, cudaEventDisableTiming) == cudaSuccess)
                 && (cudaEventCreateWithFlags(&evJoin, cudaEventDisableTiming) == cudaSuccess);
    }

    split_all<<<XBLK + WQBLK + WPBLK, 256>>>(
        x, Wqkv, Wproj, xhi, xlo, wqhi, wqlo, wphi, wplo);

    gemm_pipe<0><<<dim3(M_ / 128, J3_ / 128), 256, GP_SMEM>>>(
        xhi, xlo, wqhi, wqlo, bqkv, nullptr, kh, kl, qh, ql, vth, vtl);

    scores_exp<<<dim3(N_ / 128, N_ / 128, B_ * H_), 256, SC_SMEM>>>(
        qh, ql, kh, kl, pbh, pbl, psum);

    finalize_inv<<<(B_ * H_ * N_) / 256, 256>>>(psum, ginv);

    if (stream_ok) {
        // Fork: s2 runs the dependent chain sa_pipe -> gemm1 (tensor-bound),
        // main stream runs attn_write (DRAM-bound) fully concurrent with both.
        cudaEventRecord(evFork, 0);
        cudaStreamWaitEvent(s2, evFork, 0);

        sa_pipe<<<dim3(B_ * H_, N_ / 128), 256, SP_SMEM, s2>>>(
            pbh, pbl, vth, vtl, ginv, sahi, salo);
        gemm_pipe<1><<<dim3(M_ / 128, D_ / 128), 256, GP_SMEM, s2>>>(
            sahi, salo, wphi, wplo, bproj, out,
            nullptr, nullptr, nullptr, nullptr, nullptr, nullptr);

        attn_write<<<B_ * H_ * N_, 256>>>(pbh, pbl, ginv, attnp);

        cudaEventRecord(evJoin, s2);
        cudaStreamWaitEvent(0, evJoin, 0);
    } else {
        attn_write<<<B_ * H_ * N_, 256>>>(pbh, pbl, ginv, attnp);
        sa_pipe<<<dim3(B_ * H_, N_ / 128), 256, SP_SMEM>>>(
            pbh, pbl, vth, vtl, ginv, sahi, salo);
        gemm_pipe<1><<<dim3(M_ / 128, D_ / 128), 256, GP_SMEM>>>(
            sahi, salo, wphi, wplo, bproj, out,
            nullptr, nullptr, nullptr, nullptr, nullptr, nullptr);
    }
}